// round 14
// baseline (speedup 1.0000x reference)
#include <cuda_runtime.h>
#include <cuda_fp16.h>
#include <mma.h>
#include <math.h>
#include <stdint.h>

using namespace nvcuda;

#define TOKENS   8192
#define SEQLEN   4096
#define DMODEL   1024
#define DINNER   2048
#define NHEADS   32
#define HEADDIM  64
#define DSTATE   64
#define CHUNKL   64
#define NCHUNK   64
#define DMLP     2560
#define PROJ     9248
#define NPAD_IN  9472
#define XS_OFF   2048
#define B_OFF    4096
#define C_OFF    6144
#define DT_OFF   8192
#define TH_OFF   8224
#define YSCALE   0.015625f
#define YUNSCALE 64.0f

// ---------------- scratch (device globals: no allocation allowed) ----------------
__device__ float g_proj[75759616];
__device__ float g_xg[TOKENS * DINNER];
__device__ float g_Bn[TOKENS * DINNER];
__device__ float g_Cn[TOKENS * DINNER];
__device__ float g_dt[TOKENS * NHEADS];
__device__ float g_A[TOKENS * NHEADS];
__device__ float g_skip[TOKENS * NHEADS];
__device__ float g_cum[TOKENS * NHEADS * (DSTATE / 2)];
__device__ float g_segsum[2 * NHEADS * 8 * 32];
__device__ float g_states[2 * NHEADS * NCHUNK * HEADDIM * DSTATE];
__device__ float g_Bx[2 * NHEADS * NCHUNK * HEADDIM * DSTATE];
__device__ float g_rowsum[2 * NHEADS * NCHUNK * CHUNKL];
__device__ float g_expac[2 * NHEADS * NCHUNK * CHUNKL];
__device__ float g_dc[2 * NHEADS * NCHUNK];
__device__ float g_x2[TOKENS * DMODEL];
__device__ float g_gb[TOKENS * DMLP];
__device__ __align__(16) __half g_hh[TOKENS * DMODEL];
__device__ __align__(16) __half g_ygh[TOKENS * DINNER];
__device__ __align__(16) __half g_gbh[TOKENS * DMLP];
__device__ __align__(16) __half g_Wtin[NPAD_IN * DMODEL];
__device__ __align__(16) __half g_Wtout[DMODEL * DINNER];
__device__ __align__(16) __half g_Wtg[DMLP * DMODEL];
__device__ __align__(16) __half g_Wtu[DMLP * DMODEL];
__device__ __align__(16) __half g_Wtd[DMODEL * DMLP];

// ---------------- helpers ----------------
__device__ __forceinline__ void cp16(void* smem, const void* g) {
    uint32_t s = (uint32_t)__cvta_generic_to_shared(smem);
    asm volatile("cp.async.cg.shared.global [%0], [%1], 16;" ::"r"(s), "l"(g));
}

// ---------------- weight transpose + fp16 convert: in[K][N] -> out[Npad][K] ----------------
__global__ __launch_bounds__(256) void wtransh_kernel(const float* __restrict__ in,
                                                      __half* __restrict__ out, int K, int N) {
    __shared__ float tile[32][33];
    int n0 = blockIdx.x * 32, k0 = blockIdx.y * 32;
    int tx = threadIdx.x & 31, ty = threadIdx.x >> 5;
#pragma unroll
    for (int i = ty; i < 32; i += 8) {
        int n = n0 + tx;
        tile[i][tx] = (n < N) ? in[(size_t)(k0 + i) * N + n] : 0.f;
    }
    __syncthreads();
#pragma unroll
    for (int i = ty; i < 32; i += 8)
        out[(size_t)(n0 + i) * K + k0 + tx] = __float2half_rn(tile[tx][i]);
}

// ---------------- FP16 wmma GEMM: warp tile 64x64, 128 threads, 2x2 warp grid --------
// BM=BN=128, BK=64. mode 0: C=v; 1: C=v+Res; 2: Ch=half(silu(Res)*v); v=ascale*acc
#define AST 72
#define HBUF (128 * AST)
#define HG_SMEM (4 * HBUF * 2)  /* 73728 B */
__global__ __launch_bounds__(128, 2) void hgemm_kernel(const __half* __restrict__ A,
                                                       const __half* __restrict__ Bt,
                                                       const float* __restrict__ Res,
                                                       float* __restrict__ C,
                                                       __half* __restrict__ Ch,
                                                       int M, int N, int K, int mode,
                                                       float ascale) {
    extern __shared__ __align__(16) __half smem_h[];
    __half* As0 = smem_h;
    __half* Bs0 = smem_h + 2 * HBUF;
    float* stage = (float*)smem_h;  // [64][136] overlay

    int bm = blockIdx.y * 128, bn = blockIdx.x * 128;
    int t = threadIdx.x;
    int warp = t >> 5;
    int wm = warp & 1, wn = warp >> 1;
    int lrow = t >> 3, lcol = (t & 7) * 8;  // 16 rows x 8 cols of 16B chunks

    wmma::fragment<wmma::accumulator, 16, 16, 16, float> acc[4][4];
#pragma unroll
    for (int mi = 0; mi < 4; mi++)
#pragma unroll
        for (int nn = 0; nn < 4; nn++) wmma::fill_fragment(acc[mi][nn], 0.f);

    auto issue = [&](int buf, int k0) {
        __half* as = As0 + buf * HBUF;
        __half* bs = Bs0 + buf * HBUF;
#pragma unroll
        for (int r = 0; r < 8; r++) {
            int row = lrow + r * 16;
            cp16(&as[row * AST + lcol], A + (size_t)(bm + row) * K + k0 + lcol);
            cp16(&bs[row * AST + lcol], Bt + (size_t)(bn + row) * K + k0 + lcol);
        }
        asm volatile("cp.async.commit_group;");
    };

    int nk = K / 64;
    issue(0, 0);
    for (int it = 0; it < nk; it++) {
        int buf = it & 1;
        if (it + 1 < nk) {
            issue(buf ^ 1, (it + 1) * 64);
            asm volatile("cp.async.wait_group 1;");
        } else {
            asm volatile("cp.async.wait_group 0;");
        }
        __syncthreads();
        const __half* as = As0 + buf * HBUF;
        const __half* bs = Bs0 + buf * HBUF;
#pragma unroll
        for (int kk = 0; kk < 64; kk += 16) {
            wmma::fragment<wmma::matrix_a, 16, 16, 16, __half, wmma::row_major> af[4];
            wmma::fragment<wmma::matrix_b, 16, 16, 16, __half, wmma::col_major> bf[4];
#pragma unroll
            for (int mi = 0; mi < 4; mi++)
                wmma::load_matrix_sync(af[mi], &as[(wm * 64 + mi * 16) * AST + kk], AST);
#pragma unroll
            for (int nn = 0; nn < 4; nn++)
                wmma::load_matrix_sync(bf[nn], &bs[(wn * 64 + nn * 16) * AST + kk], AST);
#pragma unroll
            for (int mi = 0; mi < 4; mi++)
#pragma unroll
                for (int nn = 0; nn < 4; nn++)
                    wmma::mma_sync(acc[mi][nn], af[mi], bf[nn], acc[mi][nn]);
        }
        __syncthreads();
    }

    // epilogue: two 64-row passes through smem staging
    for (int p = 0; p < 2; p++) {
        __syncthreads();
        if (wm == p) {
#pragma unroll
            for (int mi = 0; mi < 4; mi++)
#pragma unroll
                for (int nn = 0; nn < 4; nn++)
                    wmma::store_matrix_sync(&stage[(mi * 16) * 136 + wn * 64 + nn * 16],
                                            acc[mi][nn], 136, wmma::mem_row_major);
        }
        __syncthreads();
#pragma unroll 4
        for (int u = t; u < 64 * 64; u += 128) {
            int row = u >> 6, c2 = (u & 63) * 2;
            int gc = bn + c2;
            if (gc < N) {
                int gr = bm + p * 64 + row;
                float v0 = stage[row * 136 + c2] * ascale;
                float v1 = stage[row * 136 + c2 + 1] * ascale;
                size_t go = (size_t)gr * N + gc;
                if (mode == 2) {
                    float r0 = Res[go], r1 = Res[go + 1];
                    v0 = r0 / (1.f + __expf(-r0)) * v0;
                    v1 = r1 / (1.f + __expf(-r1)) * v1;
                    *(__half2*)&Ch[go] = __floats2half2_rn(v0, v1);
                } else {
                    if (mode == 1) {
                        v0 += Res[go];
                        v1 += Res[go + 1];
                    }
                    *(float2*)&C[go] = make_float2(v0, v1);
                }
            }
        }
    }
}

// ---------------- rmsnorm over D=1024 (half output) ----------------
__global__ __launch_bounds__(256) void rmsnorm_kernel(const float* __restrict__ x,
                                                      const float* __restrict__ w,
                                                      __half* __restrict__ out) {
    int row = blockIdx.x;
    const float* xr = x + (size_t)row * DMODEL;
    float v[4];
    float s = 0.f;
#pragma unroll
    for (int i = 0; i < 4; i++) {
        v[i] = xr[threadIdx.x + i * 256];
        s += v[i] * v[i];
    }
    __shared__ float red[8];
#pragma unroll
    for (int o = 16; o; o >>= 1) s += __shfl_xor_sync(0xffffffffu, s, o);
    if ((threadIdx.x & 31) == 0) red[threadIdx.x >> 5] = s;
    __syncthreads();
    if (threadIdx.x == 0) {
        float tt = 0.f;
#pragma unroll
        for (int i = 0; i < 8; i++) tt += red[i];
        red[0] = rsqrtf(tt / (float)DMODEL + 1e-5f);
    }
    __syncthreads();
    float r = red[0];
#pragma unroll
    for (int i = 0; i < 4; i++) {
        int c = threadIdx.x + i * 256;
        out[(size_t)row * DMODEL + c] = __float2half_rn(v[i] * r * w[c]);
    }
}

// ---------------- per-token preprocessing ----------------
__global__ __launch_bounds__(256) void preproc_kernel(
    const float* __restrict__ proj, const float* __restrict__ A_log,
    const float* __restrict__ D_param, const float* __restrict__ dt_bias,
    const float* __restrict__ B_bias, const float* __restrict__ C_bias,
    const float* __restrict__ Bn_w, const float* __restrict__ Cn_w,
    float* __restrict__ xg, float* __restrict__ Bn, float* __restrict__ Cn,
    float* __restrict__ dtb, float* __restrict__ Ab, float* __restrict__ skipb) {
    int tok = blockIdx.x;
    const float* p = proj + (size_t)tok * PROJ;
    int warp = threadIdx.x >> 5, lane = threadIdx.x & 31;
    for (int h = warp; h < NHEADS; h += 8) {
        float xb = p[DT_OFF + h] + dt_bias[h];
        float dt = xb > 20.f ? xb : log1pf(expf(xb));
        float Av = -expf(A_log[h]) * dt;
        float alpha = expf(Av);
        float gamma = (alpha - 1.f) / (Av + 1e-6f) * 0.5f + 1.f;
        if (lane == 0) {
            dtb[tok * NHEADS + h] = dt;
            Ab[tok * NHEADS + h] = Av;
        }
        float xs0 = p[XS_OFF + h * 64 + lane];
        float xs1 = p[XS_OFF + h * 64 + 32 + lane];
        float ssum = xs0 + xs1;
#pragma unroll
        for (int o = 16; o; o >>= 1) ssum += __shfl_xor_sync(0xffffffffu, ssum, o);
        if (lane == 0) skipb[tok * NHEADS + h] = D_param[h] * ssum;
        xg[(size_t)tok * DINNER + h * 64 + lane] = xs0 * gamma;
        xg[(size_t)tok * DINNER + h * 64 + 32 + lane] = xs1 * gamma;
        float b0 = p[B_OFF + h * 64 + lane], b1 = p[B_OFF + h * 64 + 32 + lane];
        float bs = b0 * b0 + b1 * b1;
#pragma unroll
        for (int o = 16; o; o >>= 1) bs += __shfl_xor_sync(0xffffffffu, bs, o);
        float br = rsqrtf(bs / 64.f + 1e-5f);
        Bn[(size_t)tok * DINNER + h * 64 + lane] = b0 * br * Bn_w[lane] + B_bias[h * 64 + lane];
        Bn[(size_t)tok * DINNER + h * 64 + 32 + lane] =
            b1 * br * Bn_w[32 + lane] + B_bias[h * 64 + 32 + lane];
        float c0 = p[C_OFF + h * 64 + lane], c1 = p[C_OFF + h * 64 + 32 + lane];
        float cs = c0 * c0 + c1 * c1;
#pragma unroll
        for (int o = 16; o; o >>= 1) cs += __shfl_xor_sync(0xffffffffu, cs, o);
        float cr = rsqrtf(cs / 64.f + 1e-5f);
        Cn[(size_t)tok * DINNER + h * 64 + lane] = c0 * cr * Cn_w[lane] + C_bias[h * 64 + lane];
        Cn[(size_t)tok * DINNER + h * 64 + 32 + lane] =
            c1 * cr * Cn_w[32 + lane] + C_bias[h * 64 + 32 + lane];
    }
}

// ---------------- theta cumsum pass 1 ----------------
__global__ __launch_bounds__(1024) void theta_scan1(const float* __restrict__ proj,
                                                    const float* __restrict__ dtb,
                                                    float* __restrict__ cum,
                                                    float* __restrict__ segsum) {
    int blk = blockIdx.x;
    int seg = blk & 7, h = (blk >> 3) & 31, b = blk >> 8;
    int w = threadIdx.x >> 5, lane = threadIdx.x & 31;
    __shared__ float T[32][33];
    __shared__ float O[32][33];
    __shared__ float Dt[32];
    int s0 = b * SEQLEN + seg * 512;
    float carry = 0.f;
    for (int it = 0; it < 16; it++) {
        int tk = s0 + it * 32;
        T[w][lane] = proj[(size_t)(tk + w) * PROJ + TH_OFF + h * 32 + lane];
        if (w == 0) Dt[lane] = dtb[(tk + lane) * NHEADS + h];
        __syncthreads();
        float v = Dt[lane] * T[lane][w];
#pragma unroll
        for (int o = 1; o < 32; o <<= 1) {
            float tv = __shfl_up_sync(0xffffffffu, v, o);
            if (lane >= o) v += tv;
        }
        v += carry;
        float cnew = __shfl_sync(0xffffffffu, v, 31);
        O[lane][w] = v;
        __syncthreads();
        cum[(size_t)(tk + w) * 1024 + h * 32 + lane] = O[w][lane];
        carry = cnew;
    }
    if (lane == 0) segsum[blk * 32 + w] = carry;
}

// ---------------- pass 2 fused with RoPE ----------------
__global__ __launch_bounds__(1024) void theta_rope_kernel(const float* __restrict__ cum,
                                                          const float* __restrict__ segsum,
                                                          float* __restrict__ Bn,
                                                          float* __restrict__ Cn) {
    int blk = blockIdx.x;
    int seg = blk & 7, h = (blk >> 3) & 31, b = blk >> 8;
    int w = threadIdx.x >> 5, lane = threadIdx.x & 31;
    int bh8 = (b * 32 + h) * 8;
    float off = 0.f;
    for (int s = 0; s < seg; s++) off += segsum[(bh8 + s) * 32 + lane];
    int s0 = b * SEQLEN + seg * 512;
    for (int it = 0; it < 16; it++) {
        int tok = s0 + it * 32 + w;
        float ang = cum[(size_t)tok * 1024 + h * 32 + lane] + off;
        float sn, cs;
        __sincosf(ang, &sn, &cs);
        size_t base = (size_t)tok * DINNER + h * 64 + 2 * lane;
        float2 bv = *(float2*)&Bn[base];
        *(float2*)&Bn[base] = make_float2(cs * bv.x - sn * bv.y, sn * bv.x + cs * bv.y);
        float2 cv = *(float2*)&Cn[base];
        *(float2*)&Cn[base] = make_float2(cs * cv.x - sn * cv.y, sn * cv.x + cs * cv.y);
    }
}

// ---------------- per-chunk via wmma ----------------
#define CST 72
__global__ __launch_bounds__(256) void ssd_chunk_kernel(
    const float* __restrict__ xg, const float* __restrict__ Bn,
    const float* __restrict__ Ab, float* __restrict__ states, float* __restrict__ Bx,
    float* __restrict__ rowsum, float* __restrict__ expac, float* __restrict__ dc) {
    int idx = blockIdx.x;
    int c = idx & 63, h = (idx >> 6) & 31, b = idx >> 11;
    int tokbase = b * SEQLEN + c * 64;
    __shared__ __align__(16) __half Bh[64 * CST];
    __shared__ __align__(16) __half Bdh[64 * CST];
    __shared__ __align__(16) __half Xh[64 * CST];
    __shared__ float Ac[64];
    __shared__ float decs[64];
    int t = threadIdx.x;
    int lane = t & 31;
    if (t < 64) {
        float v = Ab[(tokbase + t) * NHEADS + h];
#pragma unroll
        for (int o = 1; o < 32; o <<= 1) {
            float tv = __shfl_up_sync(0xffffffffu, v, o);
            if (lane >= o) v += tv;
        }
        Ac[t] = v;
    }
    __syncthreads();
    if (t >= 32 && t < 64) Ac[t] += Ac[31];
    __syncthreads();
    float alast = Ac[63];
    if (t < 64) {
        decs[t] = __expf(alast - Ac[t]);
        expac[(size_t)idx * 64 + t] = __expf(Ac[t]);
        float rs = 64.f - (float)t;
        float act = Ac[t];
        for (int s2 = 0; s2 < t; s2++) rs += __expf(act - Ac[s2]);
        rowsum[(size_t)idx * 64 + t] = rs;
    }
    if (t == 0) dc[idx] = __expf(alast);
    __syncthreads();
    {
        int row = t >> 2, j0 = (t & 3) * 16;
        float dv = decs[row];
        const float* br = Bn + (size_t)(tokbase + row) * DINNER + h * 64;
        const float* xr = xg + (size_t)(tokbase + row) * DINNER + h * 64;
#pragma unroll
        for (int j = j0; j < j0 + 16; j += 4) {
            float4 bv = *(const float4*)&br[j];
            float4 xv = *(const float4*)&xr[j];
            *(__half2*)&Bh[row * CST + j] = __floats2half2_rn(bv.x, bv.y);
            *(__half2*)&Bh[row * CST + j + 2] = __floats2half2_rn(bv.z, bv.w);
            *(__half2*)&Bdh[row * CST + j] = __floats2half2_rn(bv.x * dv, bv.y * dv);
            *(__half2*)&Bdh[row * CST + j + 2] = __floats2half2_rn(bv.z * dv, bv.w * dv);
            *(__half2*)&Xh[row * CST + j] = __floats2half2_rn(xv.x, xv.y);
            *(__half2*)&Xh[row * CST + j + 2] = __floats2half2_rn(xv.z, xv.w);
        }
    }
    __syncthreads();
    int warp = t >> 5;
    int prod = warp >> 2, ntile = warp & 3;
    const __half* Am = prod ? Bdh : Bh;
    float* Out = (prod ? states : Bx) + (size_t)idx * 4096;
    wmma::fragment<wmma::accumulator, 16, 16, 16, float> acc[4];
#pragma unroll
    for (int pti = 0; pti < 4; pti++) wmma::fill_fragment(acc[pti], 0.f);
#pragma unroll
    for (int kc = 0; kc < 4; kc++) {
        wmma::fragment<wmma::matrix_a, 16, 16, 16, __half, wmma::col_major> af;
        wmma::load_matrix_sync(af, &Am[(kc * 16) * CST + ntile * 16], CST);
#pragma unroll
        for (int pti = 0; pti < 4; pti++) {
            wmma::fragment<wmma::matrix_b, 16, 16, 16, __half, wmma::row_major> bf;
            wmma::load_matrix_sync(bf, &Xh[(kc * 16) * CST + pti * 16], CST);
            wmma::mma_sync(acc[pti], af, bf, acc[pti]);
        }
    }
#pragma unroll
    for (int pti = 0; pti < 4; pti++)
        wmma::store_matrix_sync(&Out[(ntile * 16) * 64 + pti * 16], acc[pti], 64,
                                wmma::mem_row_major);
}

// ---------------- inter-chunk scan ----------------
__global__ __launch_bounds__(256) void ssd_scan_kernel(float* __restrict__ states,
                                                       const float* __restrict__ dc) {
    int bh = blockIdx.x >> 2, slice = blockIdx.x & 3;
    size_t off = (size_t)slice * 1024 + threadIdx.x * 4;
    float4 carry = make_float4(0.f, 0.f, 0.f, 0.f);
    for (int c = 0; c < NCHUNK; c++) {
        size_t base = ((size_t)bh * 64 + c) * 4096 + off;
        float dec = __ldg(&dc[bh * 64 + c]);
        float4 s = *(float4*)&states[base];
        carry.x = carry.x * dec + s.x;
        carry.y = carry.y * dec + s.y;
        carry.z = carry.z * dec + s.z;
        carry.w = carry.w * dec + s.w;
        *(float4*)&states[base] = carry;
    }
}

// ---------------- Y via wmma ----------------
__global__ __launch_bounds__(256) void ssd_y_kernel(
    const float* __restrict__ Cn, const float* __restrict__ Bx,
    const float* __restrict__ states, const float* __restrict__ rowsum,
    const float* __restrict__ expac, const float* __restrict__ skipb,
    const float* __restrict__ proj, __half* __restrict__ yg) {
    int idx = blockIdx.x;
    int c = idx & 63, h = (idx >> 6) & 31, b = idx >> 11;
    int tokbase = b * SEQLEN + c * 64;
    __shared__ __align__(16) __half Ch[64 * CST];
    __shared__ __align__(16) __half Bxh[64 * CST];
    __shared__ __align__(16) __half Sh[64 * CST];
    __shared__ float st1[64 * CST];
    __shared__ float st2[64 * CST];
    int t = threadIdx.x;
    size_t sb = (size_t)idx * 4096;
    {
        int row = t >> 2, j0 = (t & 3) * 16;
        const float* cr = Cn + (size_t)(tokbase + row) * DINNER + h * 64;
        const float* bxr = Bx + sb + row * 64;
        const float* sr = states + sb + row * 64;
#pragma unroll
        for (int j = j0; j < j0 + 16; j += 4) {
            float4 cv = *(const float4*)&cr[j];
            float4 bv = *(const float4*)&bxr[j];
            float4 sv = *(const float4*)&sr[j];
            *(__half2*)&Ch[row * CST + j] = __floats2half2_rn(cv.x, cv.y);
            *(__half2*)&Ch[row * CST + j + 2] = __floats2half2_rn(cv.z, cv.w);
            *(__half2*)&Bxh[row * CST + j] = __floats2half2_rn(bv.x, bv.y);
            *(__half2*)&Bxh[row * CST + j + 2] = __floats2half2_rn(bv.z, bv.w);
            *(__half2*)&Sh[row * CST + j] = __floats2half2_rn(sv.x, sv.y);
            *(__half2*)&Sh[row * CST + j + 2] = __floats2half2_rn(sv.z, sv.w);
        }
    }
    __syncthreads();
    int warp = t >> 5;
    int prod = warp >> 2, ltile = warp & 3;
    const __half* Bm = prod ? Sh : Bxh;
    float* St = prod ? st2 : st1;
    wmma::fragment<wmma::accumulator, 16, 16, 16, float> acc[4];
#pragma unroll
    for (int pti = 0; pti < 4; pti++) wmma::fill_fragment(acc[pti], 0.f);
#pragma unroll
    for (int kc = 0; kc < 4; kc++) {
        wmma::fragment<wmma::matrix_a, 16, 16, 16, __half, wmma::row_major> af;
        wmma::load_matrix_sync(af, &Ch[(ltile * 16) * CST + kc * 16], CST);
#pragma unroll
        for (int pti = 0; pti < 4; pti++) {
            wmma::fragment<wmma::matrix_b, 16, 16, 16, __half, wmma::row_major> bf;
            wmma::load_matrix_sync(bf, &Bm[(kc * 16) * CST + pti * 16], CST);
            wmma::mma_sync(acc[pti], af, bf, acc[pti]);
        }
    }
#pragma unroll
    for (int pti = 0; pti < 4; pti++)
        wmma::store_matrix_sync(&St[(ltile * 16) * CST + pti * 16], acc[pti], CST,
                                wmma::mem_row_major);
    __syncthreads();
    {
        int l = t >> 2, j0 = (t & 3) * 16;
        int tok = tokbase + l;
        float rs = rowsum[(size_t)idx * 64 + l];
        float ea = expac[(size_t)idx * 64 + l];
        float sk = skipb[tok * NHEADS + h];
        const float* zp = proj + (size_t)tok * PROJ + h * 64;
        __half* yo = yg + (size_t)tok * DINNER + h * 64;
#pragma unroll
        for (int j = j0; j < j0 + 16; j += 4) {
            float4 z4 = *(const float4*)&zp[j];
            float o[4];
            float zz[4] = {z4.x, z4.y, z4.z, z4.w};
#pragma unroll
            for (int q = 0; q < 4; q++) {
                float y = rs * st1[l * CST + j + q] + ea * st2[l * CST + j + q] + sk;
                o[q] = y * (zz[q] / (1.f + __expf(-zz[q]))) * YSCALE;
            }
            *(__half2*)&yo[j] = __floats2half2_rn(o[0], o[1]);
            *(__half2*)&yo[j + 2] = __floats2half2_rn(o[2], o[3]);
        }
    }
}

// ---------------- launch ----------------
extern "C" void kernel_launch(void* const* d_in, const int* in_sizes, int n_in,
                              void* d_out, int out_size) {
    (void)in_sizes; (void)n_in; (void)out_size;
    const float* x = (const float*)d_in[0];
    const float* n1w = (const float*)d_in[1];
    const float* n2w = (const float*)d_in[2];
    const float* W_in = (const float*)d_in[3];
    const float* W_out = (const float*)d_in[4];
    const float* A_log = (const float*)d_in[5];
    const float* Dp = (const float*)d_in[6];
    const float* dtbias = (const float*)d_in[7];
    const float* Bbias = (const float*)d_in[8];
    const float* Cbias = (const float*)d_in[9];
    const float* Bnw = (const float*)d_in[10];
    const float* Cnw = (const float*)d_in[11];
    const float* Wg = (const float*)d_in[12];
    const float* Wu = (const float*)d_in[13];
    const float* Wd = (const float*)d_in[14];
    float* out = (float*)d_out;

    float *proj, *xg, *Bn, *Cn, *dtb, *Ab, *skipb, *cum, *segsum, *states, *Bx;
    float *rowsum, *expac, *dc, *x2, *gb;
    __half *hh, *ygh, *gbh, *wtin, *wtout, *wtg, *wtu, *wtd;
    cudaGetSymbolAddress((void**)&proj, g_proj);
    cudaGetSymbolAddress((void**)&xg, g_xg);
    cudaGetSymbolAddress((void**)&Bn, g_Bn);
    cudaGetSymbolAddress((void**)&Cn, g_Cn);
    cudaGetSymbolAddress((void**)&dtb, g_dt);
    cudaGetSymbolAddress((void**)&Ab, g_A);
    cudaGetSymbolAddress((void**)&skipb, g_skip);
    cudaGetSymbolAddress((void**)&cum, g_cum);
    cudaGetSymbolAddress((void**)&segsum, g_segsum);
    cudaGetSymbolAddress((void**)&states, g_states);
    cudaGetSymbolAddress((void**)&Bx, g_Bx);
    cudaGetSymbolAddress((void**)&rowsum, g_rowsum);
    cudaGetSymbolAddress((void**)&expac, g_expac);
    cudaGetSymbolAddress((void**)&dc, g_dc);
    cudaGetSymbolAddress((void**)&x2, g_x2);
    cudaGetSymbolAddress((void**)&gb, g_gb);
    cudaGetSymbolAddress((void**)&hh, g_hh);
    cudaGetSymbolAddress((void**)&ygh, g_ygh);
    cudaGetSymbolAddress((void**)&gbh, g_gbh);
    cudaGetSymbolAddress((void**)&wtin, g_Wtin);
    cudaGetSymbolAddress((void**)&wtout, g_Wtout);
    cudaGetSymbolAddress((void**)&wtg, g_Wtg);
    cudaGetSymbolAddress((void**)&wtu, g_Wtu);
    cudaGetSymbolAddress((void**)&wtd, g_Wtd);

    static int attr_done = 0;
    if (!attr_done) {
        cudaFuncSetAttribute(hgemm_kernel, cudaFuncAttributeMaxDynamicSharedMemorySize,
                             HG_SMEM);
        attr_done = 1;
    }

    // launch order arranged so index 5 (ncu -s 5 -c 1) is the big proj GEMM
    wtransh_kernel<<<dim3(NPAD_IN / 32, DMODEL / 32), 256>>>(W_in, wtin, DMODEL, PROJ);   // 0
    wtransh_kernel<<<dim3(DMODEL / 32, DINNER / 32), 256>>>(W_out, wtout, DINNER, DMODEL); // 1
    wtransh_kernel<<<dim3(DMLP / 32, DMODEL / 32), 256>>>(Wg, wtg, DMODEL, DMLP);          // 2
    wtransh_kernel<<<dim3(DMLP / 32, DMODEL / 32), 256>>>(Wu, wtu, DMODEL, DMLP);          // 3
    rmsnorm_kernel<<<TOKENS, 256>>>(x, n1w, hh);                                           // 4
    // 5) proj = hh @ W_in   <-- profiled launch
    hgemm_kernel<<<dim3(NPAD_IN / 128, TOKENS / 128), 128, HG_SMEM>>>(
        hh, wtin, nullptr, proj, nullptr, TOKENS, PROJ, DMODEL, 0, 1.f);
    wtransh_kernel<<<dim3(DMODEL / 32, DMLP / 32), 256>>>(Wd, wtd, DMLP, DMODEL);          // 6
    // 7) per-token preprocessing
    preproc_kernel<<<TOKENS, 256>>>(proj, A_log, Dp, dtbias, Bbias, Cbias, Bnw, Cnw, xg, Bn,
                                    Cn, dtb, Ab, skipb);
    // 8/9) cumtheta scan + fused RoPE
    theta_scan1<<<2 * NHEADS * 8, 1024>>>(proj, dtb, cum, segsum);
    theta_rope_kernel<<<2 * NHEADS * 8, 1024>>>(cum, segsum, Bn, Cn);
    // 10) per-chunk states/Bx (wmma) + decay scalars
    ssd_chunk_kernel<<<2 * NHEADS * NCHUNK, 256>>>(xg, Bn, Ab, states, Bx, rowsum, expac, dc);
    // 11) inter-chunk scan
    ssd_scan_kernel<<<2 * NHEADS * 4, 256>>>(states, dc);
    // 12) Y (wmma) + skip + silu(z) gate -> ygh = half(y/64)
    ssd_y_kernel<<<2 * NHEADS * NCHUNK, 256>>>(Cn, Bx, states, rowsum, expac, skipb, proj,
                                               ygh);
    // 13) x2 = x + 64*(ygh @ W_out)
    hgemm_kernel<<<dim3(DMODEL / 128, TOKENS / 128), 128, HG_SMEM>>>(
        ygh, wtout, x, x2, nullptr, TOKENS, DMODEL, DINNER, 1, YUNSCALE);
    // 14) hh = rmsnorm(x2)
    rmsnorm_kernel<<<TOKENS, 256>>>(x2, n2w, hh);
    // 15) gb = hh @ Wg
    hgemm_kernel<<<dim3(DMLP / 128, TOKENS / 128), 128, HG_SMEM>>>(
        hh, wtg, nullptr, gb, nullptr, TOKENS, DMLP, DMODEL, 0, 1.f);
    // 16) gbh = half(silu(gb) * (hh @ Wu))
    hgemm_kernel<<<dim3(DMLP / 128, TOKENS / 128), 128, HG_SMEM>>>(
        hh, wtu, gb, nullptr, gbh, TOKENS, DMLP, DMODEL, 2, 1.f);
    // 17) out = x2 + gbh @ Wd
    hgemm_kernel<<<dim3(DMODEL / 128, TOKENS / 128), 128, HG_SMEM>>>(
        gbh, wtd, x2, out, nullptr, TOKENS, DMODEL, DMLP, 1, 1.f);
}

// round 15
// speedup vs baseline: 1.0548x; 1.0548x over previous
#include <cuda_runtime.h>
#include <cuda_fp16.h>
#include <mma.h>
#include <math.h>
#include <stdint.h>

using namespace nvcuda;

#define TOKENS   8192
#define SEQLEN   4096
#define DMODEL   1024
#define DINNER   2048
#define NHEADS   32
#define HEADDIM  64
#define DSTATE   64
#define CHUNKL   64
#define NCHUNK   64
#define DMLP     2560
#define PROJ     9248
#define NPAD_IN  9472
#define XS_OFF   2048
#define B_OFF    4096
#define C_OFF    6144
#define DT_OFF   8192
#define TH_OFF   8224
#define YSCALE   0.015625f
#define YUNSCALE 64.0f

// ---------------- scratch (device globals: no allocation allowed) ----------------
__device__ float g_proj[75759616];
__device__ float g_xg[TOKENS * DINNER];
__device__ float g_Bn[TOKENS * DINNER];
__device__ float g_Cn[TOKENS * DINNER];
__device__ float g_dt[TOKENS * NHEADS];
__device__ float g_A[TOKENS * NHEADS];
__device__ float g_skip[TOKENS * NHEADS];
__device__ float g_cum[TOKENS * NHEADS * (DSTATE / 2)];
__device__ float g_segsum[2 * NHEADS * 8 * 32];
__device__ float g_states[2 * NHEADS * NCHUNK * HEADDIM * DSTATE];
__device__ float g_Bx[2 * NHEADS * NCHUNK * HEADDIM * DSTATE];
__device__ float g_rowsum[2 * NHEADS * NCHUNK * CHUNKL];
__device__ float g_expac[2 * NHEADS * NCHUNK * CHUNKL];
__device__ float g_dc[2 * NHEADS * NCHUNK];
__device__ float g_x2[TOKENS * DMODEL];
__device__ __align__(16) float g_gb[TOKENS * DMLP];  // also hosts half gb (cast)
__device__ __align__(16) __half g_hh[TOKENS * DMODEL];
__device__ __align__(16) __half g_ygh[TOKENS * DINNER];
__device__ __align__(16) __half g_gbh[TOKENS * DMLP];
__device__ __align__(16) __half g_Wtin[NPAD_IN * DMODEL];
__device__ __align__(16) __half g_Wtout[DMODEL * DINNER];
__device__ __align__(16) __half g_Wtg[DMLP * DMODEL];
__device__ __align__(16) __half g_Wtu[DMLP * DMODEL];
__device__ __align__(16) __half g_Wtd[DMODEL * DMLP];

// ---------------- helpers ----------------
__device__ __forceinline__ void cp16(void* smem, const void* g) {
    uint32_t s = (uint32_t)__cvta_generic_to_shared(smem);
    asm volatile("cp.async.cg.shared.global [%0], [%1], 16;" ::"r"(s), "l"(g));
}

// ---------------- weight transpose + fp16 convert: in[K][N] -> out[Npad][K] ----------------
__global__ __launch_bounds__(256) void wtransh_kernel(const float* __restrict__ in,
                                                      __half* __restrict__ out, int K, int N) {
    __shared__ float tile[32][33];
    int n0 = blockIdx.x * 32, k0 = blockIdx.y * 32;
    int tx = threadIdx.x & 31, ty = threadIdx.x >> 5;
#pragma unroll
    for (int i = ty; i < 32; i += 8) {
        int n = n0 + tx;
        tile[i][tx] = (n < N) ? in[(size_t)(k0 + i) * N + n] : 0.f;
    }
    __syncthreads();
#pragma unroll
    for (int i = ty; i < 32; i += 8)
        out[(size_t)(n0 + i) * K + k0 + tx] = __float2half_rn(tile[tx][i]);
}

// ---------------- FP16 wmma GEMM (R13 config: 256 thr, 2x4 warps, 64x32 tile, BK=64) --
// mode 0: C=v; 1: C=v+Res; 2: Ch=half(silu(ResH)*v); 3: Ch=half(v)   (v = ascale*acc)
#define AST 72
#define HBUF (128 * AST)
#define HG_SMEM (4 * HBUF * 2)  /* 73728 B */
__global__ __launch_bounds__(256, 2) void hgemm_kernel(const __half* __restrict__ A,
                                                       const __half* __restrict__ Bt,
                                                       const float* __restrict__ Res,
                                                       const __half* __restrict__ ResH,
                                                       float* __restrict__ C,
                                                       __half* __restrict__ Ch,
                                                       int M, int N, int K, int mode,
                                                       float ascale) {
    extern __shared__ __align__(16) __half smem_h[];
    __half* As0 = smem_h;
    __half* Bs0 = smem_h + 2 * HBUF;
    float* stage = (float*)smem_h;

    int bm = blockIdx.y * 128, bn = blockIdx.x * 128;
    int t = threadIdx.x;
    int warp = t >> 5;
    int wm = warp & 1, wn = warp >> 1;
    int lrow = t >> 3, lcol = (t & 7) * 8;

    wmma::fragment<wmma::accumulator, 16, 16, 16, float> acc[4][2];
#pragma unroll
    for (int mi = 0; mi < 4; mi++)
#pragma unroll
        for (int nn = 0; nn < 2; nn++) wmma::fill_fragment(acc[mi][nn], 0.f);

    auto issue = [&](int buf, int k0) {
        __half* as = As0 + buf * HBUF;
        __half* bs = Bs0 + buf * HBUF;
#pragma unroll
        for (int r = 0; r < 4; r++) {
            int row = lrow + r * 32;
            cp16(&as[row * AST + lcol], A + (size_t)(bm + row) * K + k0 + lcol);
            cp16(&bs[row * AST + lcol], Bt + (size_t)(bn + row) * K + k0 + lcol);
        }
        asm volatile("cp.async.commit_group;");
    };

    int nk = K / 64;
    issue(0, 0);
    for (int it = 0; it < nk; it++) {
        int buf = it & 1;
        if (it + 1 < nk) {
            issue(buf ^ 1, (it + 1) * 64);
            asm volatile("cp.async.wait_group 1;");
        } else {
            asm volatile("cp.async.wait_group 0;");
        }
        __syncthreads();
        const __half* as = As0 + buf * HBUF;
        const __half* bs = Bs0 + buf * HBUF;
#pragma unroll
        for (int kk = 0; kk < 64; kk += 16) {
            wmma::fragment<wmma::matrix_a, 16, 16, 16, __half, wmma::row_major> af[4];
            wmma::fragment<wmma::matrix_b, 16, 16, 16, __half, wmma::col_major> bf[2];
#pragma unroll
            for (int mi = 0; mi < 4; mi++)
                wmma::load_matrix_sync(af[mi], &as[(wm * 64 + mi * 16) * AST + kk], AST);
#pragma unroll
            for (int nn = 0; nn < 2; nn++)
                wmma::load_matrix_sync(bf[nn], &bs[(wn * 32 + nn * 16) * AST + kk], AST);
#pragma unroll
            for (int mi = 0; mi < 4; mi++)
#pragma unroll
                for (int nn = 0; nn < 2; nn++)
                    wmma::mma_sync(acc[mi][nn], af[mi], bf[nn], acc[mi][nn]);
        }
        __syncthreads();
    }

    for (int p = 0; p < 2; p++) {
        __syncthreads();
        if (wm == p) {
#pragma unroll
            for (int mi = 0; mi < 4; mi++)
#pragma unroll
                for (int nn = 0; nn < 2; nn++)
                    wmma::store_matrix_sync(&stage[(mi * 16) * 136 + wn * 32 + nn * 16],
                                            acc[mi][nn], 136, wmma::mem_row_major);
        }
        __syncthreads();
#pragma unroll 4
        for (int u = t; u < 64 * 64; u += 256) {
            int row = u >> 6, c2 = (u & 63) * 2;
            int gc = bn + c2;
            if (gc < N) {
                int gr = bm + p * 64 + row;
                float v0 = stage[row * 136 + c2] * ascale;
                float v1 = stage[row * 136 + c2 + 1] * ascale;
                size_t go = (size_t)gr * N + gc;
                if (mode == 2) {
                    float2 rr = __half22float2(*(const __half2*)&ResH[go]);
                    v0 = rr.x / (1.f + __expf(-rr.x)) * v0;
                    v1 = rr.y / (1.f + __expf(-rr.y)) * v1;
                    *(__half2*)&Ch[go] = __floats2half2_rn(v0, v1);
                } else if (mode == 3) {
                    *(__half2*)&Ch[go] = __floats2half2_rn(v0, v1);
                } else {
                    if (mode == 1) {
                        v0 += Res[go];
                        v1 += Res[go + 1];
                    }
                    *(float2*)&C[go] = make_float2(v0, v1);
                }
            }
        }
    }
}

// ---------------- rmsnorm over D=1024 (half output) ----------------
__global__ __launch_bounds__(256) void rmsnorm_kernel(const float* __restrict__ x,
                                                      const float* __restrict__ w,
                                                      __half* __restrict__ out) {
    int row = blockIdx.x;
    const float* xr = x + (size_t)row * DMODEL;
    float v[4];
    float s = 0.f;
#pragma unroll
    for (int i = 0; i < 4; i++) {
        v[i] = xr[threadIdx.x + i * 256];
        s += v[i] * v[i];
    }
    __shared__ float red[8];
#pragma unroll
    for (int o = 16; o; o >>= 1) s += __shfl_xor_sync(0xffffffffu, s, o);
    if ((threadIdx.x & 31) == 0) red[threadIdx.x >> 5] = s;
    __syncthreads();
    if (threadIdx.x == 0) {
        float tt = 0.f;
#pragma unroll
        for (int i = 0; i < 8; i++) tt += red[i];
        red[0] = rsqrtf(tt / (float)DMODEL + 1e-5f);
    }
    __syncthreads();
    float r = red[0];
#pragma unroll
    for (int i = 0; i < 4; i++) {
        int c = threadIdx.x + i * 256;
        out[(size_t)row * DMODEL + c] = __float2half_rn(v[i] * r * w[c]);
    }
}

// ---------------- per-token preprocessing ----------------
__global__ __launch_bounds__(256) void preproc_kernel(
    const float* __restrict__ proj, const float* __restrict__ A_log,
    const float* __restrict__ D_param, const float* __restrict__ dt_bias,
    const float* __restrict__ B_bias, const float* __restrict__ C_bias,
    const float* __restrict__ Bn_w, const float* __restrict__ Cn_w,
    float* __restrict__ xg, float* __restrict__ Bn, float* __restrict__ Cn,
    float* __restrict__ dtb, float* __restrict__ Ab, float* __restrict__ skipb) {
    int tok = blockIdx.x;
    const float* p = proj + (size_t)tok * PROJ;
    int warp = threadIdx.x >> 5, lane = threadIdx.x & 31;
    for (int h = warp; h < NHEADS; h += 8) {
        float xb = p[DT_OFF + h] + dt_bias[h];
        float dt = xb > 20.f ? xb : log1pf(expf(xb));
        float Av = -expf(A_log[h]) * dt;
        float alpha = expf(Av);
        float gamma = (alpha - 1.f) / (Av + 1e-6f) * 0.5f + 1.f;
        if (lane == 0) {
            dtb[tok * NHEADS + h] = dt;
            Ab[tok * NHEADS + h] = Av;
        }
        float xs0 = p[XS_OFF + h * 64 + lane];
        float xs1 = p[XS_OFF + h * 64 + 32 + lane];
        float ssum = xs0 + xs1;
#pragma unroll
        for (int o = 16; o; o >>= 1) ssum += __shfl_xor_sync(0xffffffffu, ssum, o);
        if (lane == 0) skipb[tok * NHEADS + h] = D_param[h] * ssum;
        xg[(size_t)tok * DINNER + h * 64 + lane] = xs0 * gamma;
        xg[(size_t)tok * DINNER + h * 64 + 32 + lane] = xs1 * gamma;
        float b0 = p[B_OFF + h * 64 + lane], b1 = p[B_OFF + h * 64 + 32 + lane];
        float bs = b0 * b0 + b1 * b1;
#pragma unroll
        for (int o = 16; o; o >>= 1) bs += __shfl_xor_sync(0xffffffffu, bs, o);
        float br = rsqrtf(bs / 64.f + 1e-5f);
        Bn[(size_t)tok * DINNER + h * 64 + lane] = b0 * br * Bn_w[lane] + B_bias[h * 64 + lane];
        Bn[(size_t)tok * DINNER + h * 64 + 32 + lane] =
            b1 * br * Bn_w[32 + lane] + B_bias[h * 64 + 32 + lane];
        float c0 = p[C_OFF + h * 64 + lane], c1 = p[C_OFF + h * 64 + 32 + lane];
        float cs = c0 * c0 + c1 * c1;
#pragma unroll
        for (int o = 16; o; o >>= 1) cs += __shfl_xor_sync(0xffffffffu, cs, o);
        float cr = rsqrtf(cs / 64.f + 1e-5f);
        Cn[(size_t)tok * DINNER + h * 64 + lane] = c0 * cr * Cn_w[lane] + C_bias[h * 64 + lane];
        Cn[(size_t)tok * DINNER + h * 64 + 32 + lane] =
            c1 * cr * Cn_w[32 + lane] + C_bias[h * 64 + 32 + lane];
    }
}

// ---------------- theta cumsum pass 1 ----------------
__global__ __launch_bounds__(1024) void theta_scan1(const float* __restrict__ proj,
                                                    const float* __restrict__ dtb,
                                                    float* __restrict__ cum,
                                                    float* __restrict__ segsum) {
    int blk = blockIdx.x;
    int seg = blk & 7, h = (blk >> 3) & 31, b = blk >> 8;
    int w = threadIdx.x >> 5, lane = threadIdx.x & 31;
    __shared__ float T[32][33];
    __shared__ float O[32][33];
    __shared__ float Dt[32];
    int s0 = b * SEQLEN + seg * 512;
    float carry = 0.f;
    for (int it = 0; it < 16; it++) {
        int tk = s0 + it * 32;
        T[w][lane] = proj[(size_t)(tk + w) * PROJ + TH_OFF + h * 32 + lane];
        if (w == 0) Dt[lane] = dtb[(tk + lane) * NHEADS + h];
        __syncthreads();
        float v = Dt[lane] * T[lane][w];
#pragma unroll
        for (int o = 1; o < 32; o <<= 1) {
            float tv = __shfl_up_sync(0xffffffffu, v, o);
            if (lane >= o) v += tv;
        }
        v += carry;
        float cnew = __shfl_sync(0xffffffffu, v, 31);
        O[lane][w] = v;
        __syncthreads();
        cum[(size_t)(tk + w) * 1024 + h * 32 + lane] = O[w][lane];
        carry = cnew;
    }
    if (lane == 0) segsum[blk * 32 + w] = carry;
}

// ---------------- pass 2 fused with RoPE ----------------
__global__ __launch_bounds__(1024) void theta_rope_kernel(const float* __restrict__ cum,
                                                          const float* __restrict__ segsum,
                                                          float* __restrict__ Bn,
                                                          float* __restrict__ Cn) {
    int blk = blockIdx.x;
    int seg = blk & 7, h = (blk >> 3) & 31, b = blk >> 8;
    int w = threadIdx.x >> 5, lane = threadIdx.x & 31;
    int bh8 = (b * 32 + h) * 8;
    float off = 0.f;
    for (int s = 0; s < seg; s++) off += segsum[(bh8 + s) * 32 + lane];
    int s0 = b * SEQLEN + seg * 512;
    for (int it = 0; it < 16; it++) {
        int tok = s0 + it * 32 + w;
        float ang = cum[(size_t)tok * 1024 + h * 32 + lane] + off;
        float sn, cs;
        __sincosf(ang, &sn, &cs);
        size_t base = (size_t)tok * DINNER + h * 64 + 2 * lane;
        float2 bv = *(float2*)&Bn[base];
        *(float2*)&Bn[base] = make_float2(cs * bv.x - sn * bv.y, sn * bv.x + cs * bv.y);
        float2 cv = *(float2*)&Cn[base];
        *(float2*)&Cn[base] = make_float2(cs * cv.x - sn * cv.y, sn * cv.x + cs * cv.y);
    }
}

// ---------------- per-chunk via wmma ----------------
#define CST 72
__global__ __launch_bounds__(256) void ssd_chunk_kernel(
    const float* __restrict__ xg, const float* __restrict__ Bn,
    const float* __restrict__ Ab, float* __restrict__ states, float* __restrict__ Bx,
    float* __restrict__ rowsum, float* __restrict__ expac, float* __restrict__ dc) {
    int idx = blockIdx.x;
    int c = idx & 63, h = (idx >> 6) & 31, b = idx >> 11;
    int tokbase = b * SEQLEN + c * 64;
    __shared__ __align__(16) __half Bh[64 * CST];
    __shared__ __align__(16) __half Bdh[64 * CST];
    __shared__ __align__(16) __half Xh[64 * CST];
    __shared__ float Ac[64];
    __shared__ float decs[64];
    int t = threadIdx.x;
    int lane = t & 31;
    if (t < 64) {
        float v = Ab[(tokbase + t) * NHEADS + h];
#pragma unroll
        for (int o = 1; o < 32; o <<= 1) {
            float tv = __shfl_up_sync(0xffffffffu, v, o);
            if (lane >= o) v += tv;
        }
        Ac[t] = v;
    }
    __syncthreads();
    if (t >= 32 && t < 64) Ac[t] += Ac[31];
    __syncthreads();
    float alast = Ac[63];
    if (t < 64) {
        decs[t] = __expf(alast - Ac[t]);
        expac[(size_t)idx * 64 + t] = __expf(Ac[t]);
        float rs = 64.f - (float)t;
        float act = Ac[t];
        for (int s2 = 0; s2 < t; s2++) rs += __expf(act - Ac[s2]);
        rowsum[(size_t)idx * 64 + t] = rs;
    }
    if (t == 0) dc[idx] = __expf(alast);
    __syncthreads();
    {
        int row = t >> 2, j0 = (t & 3) * 16;
        float dv = decs[row];
        const float* br = Bn + (size_t)(tokbase + row) * DINNER + h * 64;
        const float* xr = xg + (size_t)(tokbase + row) * DINNER + h * 64;
#pragma unroll
        for (int j = j0; j < j0 + 16; j += 4) {
            float4 bv = *(const float4*)&br[j];
            float4 xv = *(const float4*)&xr[j];
            *(__half2*)&Bh[row * CST + j] = __floats2half2_rn(bv.x, bv.y);
            *(__half2*)&Bh[row * CST + j + 2] = __floats2half2_rn(bv.z, bv.w);
            *(__half2*)&Bdh[row * CST + j] = __floats2half2_rn(bv.x * dv, bv.y * dv);
            *(__half2*)&Bdh[row * CST + j + 2] = __floats2half2_rn(bv.z * dv, bv.w * dv);
            *(__half2*)&Xh[row * CST + j] = __floats2half2_rn(xv.x, xv.y);
            *(__half2*)&Xh[row * CST + j + 2] = __floats2half2_rn(xv.z, xv.w);
        }
    }
    __syncthreads();
    int warp = t >> 5;
    int prod = warp >> 2, ntile = warp & 3;
    const __half* Am = prod ? Bdh : Bh;
    float* Out = (prod ? states : Bx) + (size_t)idx * 4096;
    wmma::fragment<wmma::accumulator, 16, 16, 16, float> acc[4];
#pragma unroll
    for (int pti = 0; pti < 4; pti++) wmma::fill_fragment(acc[pti], 0.f);
#pragma unroll
    for (int kc = 0; kc < 4; kc++) {
        wmma::fragment<wmma::matrix_a, 16, 16, 16, __half, wmma::col_major> af;
        wmma::load_matrix_sync(af, &Am[(kc * 16) * CST + ntile * 16], CST);
#pragma unroll
        for (int pti = 0; pti < 4; pti++) {
            wmma::fragment<wmma::matrix_b, 16, 16, 16, __half, wmma::row_major> bf;
            wmma::load_matrix_sync(bf, &Xh[(kc * 16) * CST + pti * 16], CST);
            wmma::mma_sync(acc[pti], af, bf, acc[pti]);
        }
    }
#pragma unroll
    for (int pti = 0; pti < 4; pti++)
        wmma::store_matrix_sync(&Out[(ntile * 16) * 64 + pti * 16], acc[pti], 64,
                                wmma::mem_row_major);
}

// ---------------- inter-chunk scan ----------------
__global__ __launch_bounds__(256) void ssd_scan_kernel(float* __restrict__ states,
                                                       const float* __restrict__ dc) {
    int bh = blockIdx.x >> 2, slice = blockIdx.x & 3;
    size_t off = (size_t)slice * 1024 + threadIdx.x * 4;
    float4 carry = make_float4(0.f, 0.f, 0.f, 0.f);
    for (int c = 0; c < NCHUNK; c++) {
        size_t base = ((size_t)bh * 64 + c) * 4096 + off;
        float dec = __ldg(&dc[bh * 64 + c]);
        float4 s = *(float4*)&states[base];
        carry.x = carry.x * dec + s.x;
        carry.y = carry.y * dec + s.y;
        carry.z = carry.z * dec + s.z;
        carry.w = carry.w * dec + s.w;
        *(float4*)&states[base] = carry;
    }
}

// ---------------- Y via wmma ----------------
__global__ __launch_bounds__(256) void ssd_y_kernel(
    const float* __restrict__ Cn, const float* __restrict__ Bx,
    const float* __restrict__ states, const float* __restrict__ rowsum,
    const float* __restrict__ expac, const float* __restrict__ skipb,
    const float* __restrict__ proj, __half* __restrict__ yg) {
    int idx = blockIdx.x;
    int c = idx & 63, h = (idx >> 6) & 31, b = idx >> 11;
    int tokbase = b * SEQLEN + c * 64;
    __shared__ __align__(16) __half Ch[64 * CST];
    __shared__ __align__(16) __half Bxh[64 * CST];
    __shared__ __align__(16) __half Sh[64 * CST];
    __shared__ float st1[64 * CST];
    __shared__ float st2[64 * CST];
    int t = threadIdx.x;
    size_t sb = (size_t)idx * 4096;
    {
        int row = t >> 2, j0 = (t & 3) * 16;
        const float* cr = Cn + (size_t)(tokbase + row) * DINNER + h * 64;
        const float* bxr = Bx + sb + row * 64;
        const float* sr = states + sb + row * 64;
#pragma unroll
        for (int j = j0; j < j0 + 16; j += 4) {
            float4 cv = *(const float4*)&cr[j];
            float4 bv = *(const float4*)&bxr[j];
            float4 sv = *(const float4*)&sr[j];
            *(__half2*)&Ch[row * CST + j] = __floats2half2_rn(cv.x, cv.y);
            *(__half2*)&Ch[row * CST + j + 2] = __floats2half2_rn(cv.z, cv.w);
            *(__half2*)&Bxh[row * CST + j] = __floats2half2_rn(bv.x, bv.y);
            *(__half2*)&Bxh[row * CST + j + 2] = __floats2half2_rn(bv.z, bv.w);
            *(__half2*)&Sh[row * CST + j] = __floats2half2_rn(sv.x, sv.y);
            *(__half2*)&Sh[row * CST + j + 2] = __floats2half2_rn(sv.z, sv.w);
        }
    }
    __syncthreads();
    int warp = t >> 5;
    int prod = warp >> 2, ltile = warp & 3;
    const __half* Bm = prod ? Sh : Bxh;
    float* St = prod ? st2 : st1;
    wmma::fragment<wmma::accumulator, 16, 16, 16, float> acc[4];
#pragma unroll
    for (int pti = 0; pti < 4; pti++) wmma::fill_fragment(acc[pti], 0.f);
#pragma unroll
    for (int kc = 0; kc < 4; kc++) {
        wmma::fragment<wmma::matrix_a, 16, 16, 16, __half, wmma::row_major> af;
        wmma::load_matrix_sync(af, &Ch[(ltile * 16) * CST + kc * 16], CST);
#pragma unroll
        for (int pti = 0; pti < 4; pti++) {
            wmma::fragment<wmma::matrix_b, 16, 16, 16, __half, wmma::row_major> bf;
            wmma::load_matrix_sync(bf, &Bm[(kc * 16) * CST + pti * 16], CST);
            wmma::mma_sync(acc[pti], af, bf, acc[pti]);
        }
    }
#pragma unroll
    for (int pti = 0; pti < 4; pti++)
        wmma::store_matrix_sync(&St[(ltile * 16) * CST + pti * 16], acc[pti], CST,
                                wmma::mem_row_major);
    __syncthreads();
    {
        int l = t >> 2, j0 = (t & 3) * 16;
        int tok = tokbase + l;
        float rs = rowsum[(size_t)idx * 64 + l];
        float ea = expac[(size_t)idx * 64 + l];
        float sk = skipb[tok * NHEADS + h];
        const float* zp = proj + (size_t)tok * PROJ + h * 64;
        __half* yo = yg + (size_t)tok * DINNER + h * 64;
#pragma unroll
        for (int j = j0; j < j0 + 16; j += 4) {
            float4 z4 = *(const float4*)&zp[j];
            float o[4];
            float zz[4] = {z4.x, z4.y, z4.z, z4.w};
#pragma unroll
            for (int q = 0; q < 4; q++) {
                float y = rs * st1[l * CST + j + q] + ea * st2[l * CST + j + q] + sk;
                o[q] = y * (zz[q] / (1.f + __expf(-zz[q]))) * YSCALE;
            }
            *(__half2*)&yo[j] = __floats2half2_rn(o[0], o[1]);
            *(__half2*)&yo[j + 2] = __floats2half2_rn(o[2], o[3]);
        }
    }
}

// ---------------- launch ----------------
extern "C" void kernel_launch(void* const* d_in, const int* in_sizes, int n_in,
                              void* d_out, int out_size) {
    (void)in_sizes; (void)n_in; (void)out_size;
    const float* x = (const float*)d_in[0];
    const float* n1w = (const float*)d_in[1];
    const float* n2w = (const float*)d_in[2];
    const float* W_in = (const float*)d_in[3];
    const float* W_out = (const float*)d_in[4];
    const float* A_log = (const float*)d_in[5];
    const float* Dp = (const float*)d_in[6];
    const float* dtbias = (const float*)d_in[7];
    const float* Bbias = (const float*)d_in[8];
    const float* Cbias = (const float*)d_in[9];
    const float* Bnw = (const float*)d_in[10];
    const float* Cnw = (const float*)d_in[11];
    const float* Wg = (const float*)d_in[12];
    const float* Wu = (const float*)d_in[13];
    const float* Wd = (const float*)d_in[14];
    float* out = (float*)d_out;

    float *proj, *xg, *Bn, *Cn, *dtb, *Ab, *skipb, *cum, *segsum, *states, *Bx;
    float *rowsum, *expac, *dc, *x2, *gb;
    __half *hh, *ygh, *gbh, *wtin, *wtout, *wtg, *wtu, *wtd;
    cudaGetSymbolAddress((void**)&proj, g_proj);
    cudaGetSymbolAddress((void**)&xg, g_xg);
    cudaGetSymbolAddress((void**)&Bn, g_Bn);
    cudaGetSymbolAddress((void**)&Cn, g_Cn);
    cudaGetSymbolAddress((void**)&dtb, g_dt);
    cudaGetSymbolAddress((void**)&Ab, g_A);
    cudaGetSymbolAddress((void**)&skipb, g_skip);
    cudaGetSymbolAddress((void**)&cum, g_cum);
    cudaGetSymbolAddress((void**)&segsum, g_segsum);
    cudaGetSymbolAddress((void**)&states, g_states);
    cudaGetSymbolAddress((void**)&Bx, g_Bx);
    cudaGetSymbolAddress((void**)&rowsum, g_rowsum);
    cudaGetSymbolAddress((void**)&expac, g_expac);
    cudaGetSymbolAddress((void**)&dc, g_dc);
    cudaGetSymbolAddress((void**)&x2, g_x2);
    cudaGetSymbolAddress((void**)&gb, g_gb);
    cudaGetSymbolAddress((void**)&hh, g_hh);
    cudaGetSymbolAddress((void**)&ygh, g_ygh);
    cudaGetSymbolAddress((void**)&gbh, g_gbh);
    cudaGetSymbolAddress((void**)&wtin, g_Wtin);
    cudaGetSymbolAddress((void**)&wtout, g_Wtout);
    cudaGetSymbolAddress((void**)&wtg, g_Wtg);
    cudaGetSymbolAddress((void**)&wtu, g_Wtu);
    cudaGetSymbolAddress((void**)&wtd, g_Wtd);
    __half* gbhalf = (__half*)gb;  // half gb lives in the float buffer (oversized)

    static int attr_done = 0;
    if (!attr_done) {
        cudaFuncSetAttribute(hgemm_kernel, cudaFuncAttributeMaxDynamicSharedMemorySize,
                             HG_SMEM);
        attr_done = 1;
    }

    wtransh_kernel<<<dim3(NPAD_IN / 32, DMODEL / 32), 256>>>(W_in, wtin, DMODEL, PROJ);
    wtransh_kernel<<<dim3(DMODEL / 32, DINNER / 32), 256>>>(W_out, wtout, DINNER, DMODEL);
    wtransh_kernel<<<dim3(DMLP / 32, DMODEL / 32), 256>>>(Wg, wtg, DMODEL, DMLP);
    wtransh_kernel<<<dim3(DMLP / 32, DMODEL / 32), 256>>>(Wu, wtu, DMODEL, DMLP);
    wtransh_kernel<<<dim3(DMODEL / 32, DMLP / 32), 256>>>(Wd, wtd, DMLP, DMODEL);

    // 1) hh = rmsnorm(x)
    rmsnorm_kernel<<<TOKENS, 256>>>(x, n1w, hh);
    // 2) proj = hh @ W_in
    hgemm_kernel<<<dim3(NPAD_IN / 128, TOKENS / 128), 256, HG_SMEM>>>(
        hh, wtin, nullptr, nullptr, proj, nullptr, TOKENS, PROJ, DMODEL, 0, 1.f);
    // 3) per-token preprocessing
    preproc_kernel<<<TOKENS, 256>>>(proj, A_log, Dp, dtbias, Bbias, Cbias, Bnw, Cnw, xg, Bn,
                                    Cn, dtb, Ab, skipb);
    // 4) cumtheta scan + fused RoPE
    theta_scan1<<<2 * NHEADS * 8, 1024>>>(proj, dtb, cum, segsum);
    theta_rope_kernel<<<2 * NHEADS * 8, 1024>>>(cum, segsum, Bn, Cn);
    // 5) per-chunk states/Bx (wmma) + decay scalars
    ssd_chunk_kernel<<<2 * NHEADS * NCHUNK, 256>>>(xg, Bn, Ab, states, Bx, rowsum, expac, dc);
    // 6) inter-chunk scan
    ssd_scan_kernel<<<2 * NHEADS * 4, 256>>>(states, dc);
    // 7) Y (wmma) + skip + silu(z) gate -> ygh = half(y/64)
    ssd_y_kernel<<<2 * NHEADS * NCHUNK, 256>>>(Cn, Bx, states, rowsum, expac, skipb, proj,
                                               ygh);
    // 8) x2 = x + 64*(ygh @ W_out)
    hgemm_kernel<<<dim3(DMODEL / 128, TOKENS / 128), 256, HG_SMEM>>>(
        ygh, wtout, x, nullptr, x2, nullptr, TOKENS, DMODEL, DINNER, 1, YUNSCALE);
    // 9) hh = rmsnorm(x2)
    rmsnorm_kernel<<<TOKENS, 256>>>(x2, n2w, hh);
    // 10) gbhalf = half(hh @ Wg)   (mode 3: half store, no fp32 round trip)
    hgemm_kernel<<<dim3(DMLP / 128, TOKENS / 128), 256, HG_SMEM>>>(
        hh, wtg, nullptr, nullptr, nullptr, gbhalf, TOKENS, DMLP, DMODEL, 3, 1.f);
    // 11) gbh = half(silu(gbhalf) * (hh @ Wu))   (mode 2: half gate operand)
    hgemm_kernel<<<dim3(DMLP / 128, TOKENS / 128), 256, HG_SMEM>>>(
        hh, wtu, nullptr, gbhalf, nullptr, gbh, TOKENS, DMLP, DMODEL, 2, 1.f);
    // 12) out = x2 + gbh @ Wd
    hgemm_kernel<<<dim3(DMODEL / 128, TOKENS / 128), 256, HG_SMEM>>>(
        gbh, wtd, x2, nullptr, out, nullptr, TOKENS, DMODEL, DMLP, 1, 1.f);
}

// round 16
// speedup vs baseline: 1.0697x; 1.0141x over previous
#include <cuda_runtime.h>
#include <cuda_fp16.h>
#include <mma.h>
#include <math.h>
#include <stdint.h>

using namespace nvcuda;

#define TOKENS   8192
#define SEQLEN   4096
#define DMODEL   1024
#define DINNER   2048
#define NHEADS   32
#define HEADDIM  64
#define DSTATE   64
#define CHUNKL   64
#define NCHUNK   64
#define DMLP     2560
#define PROJ     9248
#define NPAD_IN  9472
#define XS_OFF   2048
#define B_OFF    4096
#define C_OFF    6144
#define DT_OFF   8192
#define TH_OFF   8224
#define YSCALE   0.015625f
#define YUNSCALE 64.0f

// ---------------- scratch (device globals: no allocation allowed) ----------------
__device__ float g_proj[75759616];
__device__ float g_xg[TOKENS * DINNER];
__device__ float g_Bn[TOKENS * DINNER];
__device__ float g_Cn[TOKENS * DINNER];
__device__ float g_dt[TOKENS * NHEADS];
__device__ float g_A[TOKENS * NHEADS];
__device__ float g_skip[TOKENS * NHEADS];
__device__ float g_cum[TOKENS * NHEADS * (DSTATE / 2)];
__device__ float g_segsum[2 * NHEADS * 8 * 32];
__device__ float g_states[2 * NHEADS * NCHUNK * HEADDIM * DSTATE];
__device__ float g_Bx[2 * NHEADS * NCHUNK * HEADDIM * DSTATE];
__device__ float g_rowsum[2 * NHEADS * NCHUNK * CHUNKL];
__device__ float g_expac[2 * NHEADS * NCHUNK * CHUNKL];
__device__ float g_dc[2 * NHEADS * NCHUNK];
__device__ float g_x2[TOKENS * DMODEL];
__device__ __align__(16) float g_gb[TOKENS * DMLP];  // also hosts half gb (cast)
__device__ __align__(16) __half g_hh[TOKENS * DMODEL];
__device__ __align__(16) __half g_ygh[TOKENS * DINNER];
__device__ __align__(16) __half g_gbh[TOKENS * DMLP];
__device__ __align__(16) __half g_Wtin[NPAD_IN * DMODEL];
__device__ __align__(16) __half g_Wtout[DMODEL * DINNER];
__device__ __align__(16) __half g_Wtg[DMLP * DMODEL];
__device__ __align__(16) __half g_Wtu[DMLP * DMODEL];
__device__ __align__(16) __half g_Wtd[DMODEL * DMLP];

// ---------------- helpers ----------------
__device__ __forceinline__ void cp16(void* smem, const void* g) {
    uint32_t s = (uint32_t)__cvta_generic_to_shared(smem);
    asm volatile("cp.async.cg.shared.global [%0], [%1], 16;" ::"r"(s), "l"(g));
}

// ---------------- weight transpose + fp16 convert: in[K][N] -> out[Npad][K] ----------------
__global__ __launch_bounds__(256) void wtransh_kernel(const float* __restrict__ in,
                                                      __half* __restrict__ out, int K, int N) {
    __shared__ float tile[32][33];
    int n0 = blockIdx.x * 32, k0 = blockIdx.y * 32;
    int tx = threadIdx.x & 31, ty = threadIdx.x >> 5;
#pragma unroll
    for (int i = ty; i < 32; i += 8) {
        int n = n0 + tx;
        tile[i][tx] = (n < N) ? in[(size_t)(k0 + i) * N + n] : 0.f;
    }
    __syncthreads();
#pragma unroll
    for (int i = ty; i < 32; i += 8)
        out[(size_t)(n0 + i) * K + k0 + tx] = __float2half_rn(tile[tx][i]);
}

// ---------------- FP16 wmma GEMM (256 thr, 2x4 warps, 64x32 tile, BK=64) --------------
// mode 0: C=v; 1: C=v+Res; 2: Ch=half(silu(ResH)*v); 3: Ch=half(v)   (v = ascale*acc)
// modes 0/1 on full N-tiles use direct fragment stores (no smem staging).
#define AST 72
#define HBUF (128 * AST)
#define HG_SMEM (4 * HBUF * 2)  /* 73728 B */
__global__ __launch_bounds__(256, 2) void hgemm_kernel(const __half* __restrict__ A,
                                                       const __half* __restrict__ Bt,
                                                       const float* __restrict__ Res,
                                                       const __half* __restrict__ ResH,
                                                       float* __restrict__ C,
                                                       __half* __restrict__ Ch,
                                                       int M, int N, int K, int mode,
                                                       float ascale) {
    extern __shared__ __align__(16) __half smem_h[];
    __half* As0 = smem_h;
    __half* Bs0 = smem_h + 2 * HBUF;
    float* stage = (float*)smem_h;

    int bm = blockIdx.y * 128, bn = blockIdx.x * 128;
    int t = threadIdx.x;
    int warp = t >> 5;
    int wm = warp & 1, wn = warp >> 1;
    int lrow = t >> 3, lcol = (t & 7) * 8;

    wmma::fragment<wmma::accumulator, 16, 16, 16, float> acc[4][2];
#pragma unroll
    for (int mi = 0; mi < 4; mi++)
#pragma unroll
        for (int nn = 0; nn < 2; nn++) wmma::fill_fragment(acc[mi][nn], 0.f);

    auto issue = [&](int buf, int k0) {
        __half* as = As0 + buf * HBUF;
        __half* bs = Bs0 + buf * HBUF;
#pragma unroll
        for (int r = 0; r < 4; r++) {
            int row = lrow + r * 32;
            cp16(&as[row * AST + lcol], A + (size_t)(bm + row) * K + k0 + lcol);
            cp16(&bs[row * AST + lcol], Bt + (size_t)(bn + row) * K + k0 + lcol);
        }
        asm volatile("cp.async.commit_group;");
    };

    int nk = K / 64;
    issue(0, 0);
    for (int it = 0; it < nk; it++) {
        int buf = it & 1;
        if (it + 1 < nk) {
            issue(buf ^ 1, (it + 1) * 64);
            asm volatile("cp.async.wait_group 1;");
        } else {
            asm volatile("cp.async.wait_group 0;");
        }
        __syncthreads();
        const __half* as = As0 + buf * HBUF;
        const __half* bs = Bs0 + buf * HBUF;
#pragma unroll
        for (int kk = 0; kk < 64; kk += 16) {
            wmma::fragment<wmma::matrix_a, 16, 16, 16, __half, wmma::row_major> af[4];
            wmma::fragment<wmma::matrix_b, 16, 16, 16, __half, wmma::col_major> bf[2];
#pragma unroll
            for (int mi = 0; mi < 4; mi++)
                wmma::load_matrix_sync(af[mi], &as[(wm * 64 + mi * 16) * AST + kk], AST);
#pragma unroll
            for (int nn = 0; nn < 2; nn++)
                wmma::load_matrix_sync(bf[nn], &bs[(wn * 32 + nn * 16) * AST + kk], AST);
#pragma unroll
            for (int mi = 0; mi < 4; mi++)
#pragma unroll
                for (int nn = 0; nn < 2; nn++)
                    wmma::mma_sync(acc[mi][nn], af[mi], bf[nn], acc[mi][nn]);
        }
        __syncthreads();
    }

    // -------- fast path: direct fragment stores (float output, full N tile) --------
    if (mode <= 1 && bn + 128 <= N) {
#pragma unroll
        for (int mi = 0; mi < 4; mi++) {
#pragma unroll
            for (int nn = 0; nn < 2; nn++) {
                size_t off = (size_t)(bm + wm * 64 + mi * 16) * N + bn + wn * 32 + nn * 16;
                if (mode == 1) {
                    wmma::fragment<wmma::accumulator, 16, 16, 16, float> rf;
                    wmma::load_matrix_sync(rf, Res + off, N, wmma::mem_row_major);
#pragma unroll
                    for (int e = 0; e < rf.num_elements; e++)
                        acc[mi][nn].x[e] = acc[mi][nn].x[e] * ascale + rf.x[e];
                } else if (ascale != 1.f) {
#pragma unroll
                    for (int e = 0; e < acc[mi][nn].num_elements; e++)
                        acc[mi][nn].x[e] *= ascale;
                }
                wmma::store_matrix_sync(C + off, acc[mi][nn], N, wmma::mem_row_major);
            }
        }
        return;
    }

    // -------- staged path (half outputs / partial tiles) --------
    for (int p = 0; p < 2; p++) {
        __syncthreads();
        if (wm == p) {
#pragma unroll
            for (int mi = 0; mi < 4; mi++)
#pragma unroll
                for (int nn = 0; nn < 2; nn++)
                    wmma::store_matrix_sync(&stage[(mi * 16) * 136 + wn * 32 + nn * 16],
                                            acc[mi][nn], 136, wmma::mem_row_major);
        }
        __syncthreads();
#pragma unroll 4
        for (int u = t; u < 64 * 64; u += 256) {
            int row = u >> 6, c2 = (u & 63) * 2;
            int gc = bn + c2;
            if (gc < N) {
                int gr = bm + p * 64 + row;
                float v0 = stage[row * 136 + c2] * ascale;
                float v1 = stage[row * 136 + c2 + 1] * ascale;
                size_t go = (size_t)gr * N + gc;
                if (mode == 2) {
                    float2 rr = __half22float2(*(const __half2*)&ResH[go]);
                    v0 = rr.x / (1.f + __expf(-rr.x)) * v0;
                    v1 = rr.y / (1.f + __expf(-rr.y)) * v1;
                    *(__half2*)&Ch[go] = __floats2half2_rn(v0, v1);
                } else if (mode == 3) {
                    *(__half2*)&Ch[go] = __floats2half2_rn(v0, v1);
                } else {
                    if (mode == 1) {
                        v0 += Res[go];
                        v1 += Res[go + 1];
                    }
                    *(float2*)&C[go] = make_float2(v0, v1);
                }
            }
        }
    }
}

// ---------------- rmsnorm over D=1024 (half output) ----------------
__global__ __launch_bounds__(256) void rmsnorm_kernel(const float* __restrict__ x,
                                                      const float* __restrict__ w,
                                                      __half* __restrict__ out) {
    int row = blockIdx.x;
    const float* xr = x + (size_t)row * DMODEL;
    float v[4];
    float s = 0.f;
#pragma unroll
    for (int i = 0; i < 4; i++) {
        v[i] = xr[threadIdx.x + i * 256];
        s += v[i] * v[i];
    }
    __shared__ float red[8];
#pragma unroll
    for (int o = 16; o; o >>= 1) s += __shfl_xor_sync(0xffffffffu, s, o);
    if ((threadIdx.x & 31) == 0) red[threadIdx.x >> 5] = s;
    __syncthreads();
    if (threadIdx.x == 0) {
        float tt = 0.f;
#pragma unroll
        for (int i = 0; i < 8; i++) tt += red[i];
        red[0] = rsqrtf(tt / (float)DMODEL + 1e-5f);
    }
    __syncthreads();
    float r = red[0];
#pragma unroll
    for (int i = 0; i < 4; i++) {
        int c = threadIdx.x + i * 256;
        out[(size_t)row * DMODEL + c] = __float2half_rn(v[i] * r * w[c]);
    }
}

// ---------------- per-token preprocessing ----------------
__global__ __launch_bounds__(256) void preproc_kernel(
    const float* __restrict__ proj, const float* __restrict__ A_log,
    const float* __restrict__ D_param, const float* __restrict__ dt_bias,
    const float* __restrict__ B_bias, const float* __restrict__ C_bias,
    const float* __restrict__ Bn_w, const float* __restrict__ Cn_w,
    float* __restrict__ xg, float* __restrict__ Bn, float* __restrict__ Cn,
    float* __restrict__ dtb, float* __restrict__ Ab, float* __restrict__ skipb) {
    int tok = blockIdx.x;
    const float* p = proj + (size_t)tok * PROJ;
    int warp = threadIdx.x >> 5, lane = threadIdx.x & 31;
    for (int h = warp; h < NHEADS; h += 8) {
        float xb = p[DT_OFF + h] + dt_bias[h];
        float dt = xb > 20.f ? xb : log1pf(expf(xb));
        float Av = -expf(A_log[h]) * dt;
        float alpha = expf(Av);
        float gamma = (alpha - 1.f) / (Av + 1e-6f) * 0.5f + 1.f;
        if (lane == 0) {
            dtb[tok * NHEADS + h] = dt;
            Ab[tok * NHEADS + h] = Av;
        }
        float xs0 = p[XS_OFF + h * 64 + lane];
        float xs1 = p[XS_OFF + h * 64 + 32 + lane];
        float ssum = xs0 + xs1;
#pragma unroll
        for (int o = 16; o; o >>= 1) ssum += __shfl_xor_sync(0xffffffffu, ssum, o);
        if (lane == 0) skipb[tok * NHEADS + h] = D_param[h] * ssum;
        xg[(size_t)tok * DINNER + h * 64 + lane] = xs0 * gamma;
        xg[(size_t)tok * DINNER + h * 64 + 32 + lane] = xs1 * gamma;
        float b0 = p[B_OFF + h * 64 + lane], b1 = p[B_OFF + h * 64 + 32 + lane];
        float bs = b0 * b0 + b1 * b1;
#pragma unroll
        for (int o = 16; o; o >>= 1) bs += __shfl_xor_sync(0xffffffffu, bs, o);
        float br = rsqrtf(bs / 64.f + 1e-5f);
        Bn[(size_t)tok * DINNER + h * 64 + lane] = b0 * br * Bn_w[lane] + B_bias[h * 64 + lane];
        Bn[(size_t)tok * DINNER + h * 64 + 32 + lane] =
            b1 * br * Bn_w[32 + lane] + B_bias[h * 64 + 32 + lane];
        float c0 = p[C_OFF + h * 64 + lane], c1 = p[C_OFF + h * 64 + 32 + lane];
        float cs = c0 * c0 + c1 * c1;
#pragma unroll
        for (int o = 16; o; o >>= 1) cs += __shfl_xor_sync(0xffffffffu, cs, o);
        float cr = rsqrtf(cs / 64.f + 1e-5f);
        Cn[(size_t)tok * DINNER + h * 64 + lane] = c0 * cr * Cn_w[lane] + C_bias[h * 64 + lane];
        Cn[(size_t)tok * DINNER + h * 64 + 32 + lane] =
            c1 * cr * Cn_w[32 + lane] + C_bias[h * 64 + 32 + lane];
    }
}

// ---------------- theta cumsum pass 1 ----------------
__global__ __launch_bounds__(1024) void theta_scan1(const float* __restrict__ proj,
                                                    const float* __restrict__ dtb,
                                                    float* __restrict__ cum,
                                                    float* __restrict__ segsum) {
    int blk = blockIdx.x;
    int seg = blk & 7, h = (blk >> 3) & 31, b = blk >> 8;
    int w = threadIdx.x >> 5, lane = threadIdx.x & 31;
    __shared__ float T[32][33];
    __shared__ float O[32][33];
    __shared__ float Dt[32];
    int s0 = b * SEQLEN + seg * 512;
    float carry = 0.f;
    for (int it = 0; it < 16; it++) {
        int tk = s0 + it * 32;
        T[w][lane] = proj[(size_t)(tk + w) * PROJ + TH_OFF + h * 32 + lane];
        if (w == 0) Dt[lane] = dtb[(tk + lane) * NHEADS + h];
        __syncthreads();
        float v = Dt[lane] * T[lane][w];
#pragma unroll
        for (int o = 1; o < 32; o <<= 1) {
            float tv = __shfl_up_sync(0xffffffffu, v, o);
            if (lane >= o) v += tv;
        }
        v += carry;
        float cnew = __shfl_sync(0xffffffffu, v, 31);
        O[lane][w] = v;
        __syncthreads();
        cum[(size_t)(tk + w) * 1024 + h * 32 + lane] = O[w][lane];
        carry = cnew;
    }
    if (lane == 0) segsum[blk * 32 + w] = carry;
}

// ---------------- pass 2 fused with RoPE ----------------
__global__ __launch_bounds__(1024) void theta_rope_kernel(const float* __restrict__ cum,
                                                          const float* __restrict__ segsum,
                                                          float* __restrict__ Bn,
                                                          float* __restrict__ Cn) {
    int blk = blockIdx.x;
    int seg = blk & 7, h = (blk >> 3) & 31, b = blk >> 8;
    int w = threadIdx.x >> 5, lane = threadIdx.x & 31;
    int bh8 = (b * 32 + h) * 8;
    float off = 0.f;
    for (int s = 0; s < seg; s++) off += segsum[(bh8 + s) * 32 + lane];
    int s0 = b * SEQLEN + seg * 512;
    for (int it = 0; it < 16; it++) {
        int tok = s0 + it * 32 + w;
        float ang = cum[(size_t)tok * 1024 + h * 32 + lane] + off;
        float sn, cs;
        __sincosf(ang, &sn, &cs);
        size_t base = (size_t)tok * DINNER + h * 64 + 2 * lane;
        float2 bv = *(float2*)&Bn[base];
        *(float2*)&Bn[base] = make_float2(cs * bv.x - sn * bv.y, sn * bv.x + cs * bv.y);
        float2 cv = *(float2*)&Cn[base];
        *(float2*)&Cn[base] = make_float2(cs * cv.x - sn * cv.y, sn * cv.x + cs * cv.y);
    }
}

// ---------------- per-chunk via wmma ----------------
#define CST 72
__global__ __launch_bounds__(256) void ssd_chunk_kernel(
    const float* __restrict__ xg, const float* __restrict__ Bn,
    const float* __restrict__ Ab, float* __restrict__ states, float* __restrict__ Bx,
    float* __restrict__ rowsum, float* __restrict__ expac, float* __restrict__ dc) {
    int idx = blockIdx.x;
    int c = idx & 63, h = (idx >> 6) & 31, b = idx >> 11;
    int tokbase = b * SEQLEN + c * 64;
    __shared__ __align__(16) __half Bh[64 * CST];
    __shared__ __align__(16) __half Bdh[64 * CST];
    __shared__ __align__(16) __half Xh[64 * CST];
    __shared__ float Ac[64];
    __shared__ float decs[64];
    int t = threadIdx.x;
    int lane = t & 31;
    if (t < 64) {
        float v = Ab[(tokbase + t) * NHEADS + h];
#pragma unroll
        for (int o = 1; o < 32; o <<= 1) {
            float tv = __shfl_up_sync(0xffffffffu, v, o);
            if (lane >= o) v += tv;
        }
        Ac[t] = v;
    }
    __syncthreads();
    if (t >= 32 && t < 64) Ac[t] += Ac[31];
    __syncthreads();
    float alast = Ac[63];
    if (t < 64) {
        decs[t] = __expf(alast - Ac[t]);
        expac[(size_t)idx * 64 + t] = __expf(Ac[t]);
        float rs = 64.f - (float)t;
        float act = Ac[t];
        for (int s2 = 0; s2 < t; s2++) rs += __expf(act - Ac[s2]);
        rowsum[(size_t)idx * 64 + t] = rs;
    }
    if (t == 0) dc[idx] = __expf(alast);
    __syncthreads();
    {
        int row = t >> 2, j0 = (t & 3) * 16;
        float dv = decs[row];
        const float* br = Bn + (size_t)(tokbase + row) * DINNER + h * 64;
        const float* xr = xg + (size_t)(tokbase + row) * DINNER + h * 64;
#pragma unroll
        for (int j = j0; j < j0 + 16; j += 4) {
            float4 bv = *(const float4*)&br[j];
            float4 xv = *(const float4*)&xr[j];
            *(__half2*)&Bh[row * CST + j] = __floats2half2_rn(bv.x, bv.y);
            *(__half2*)&Bh[row * CST + j + 2] = __floats2half2_rn(bv.z, bv.w);
            *(__half2*)&Bdh[row * CST + j] = __floats2half2_rn(bv.x * dv, bv.y * dv);
            *(__half2*)&Bdh[row * CST + j + 2] = __floats2half2_rn(bv.z * dv, bv.w * dv);
            *(__half2*)&Xh[row * CST + j] = __floats2half2_rn(xv.x, xv.y);
            *(__half2*)&Xh[row * CST + j + 2] = __floats2half2_rn(xv.z, xv.w);
        }
    }
    __syncthreads();
    int warp = t >> 5;
    int prod = warp >> 2, ntile = warp & 3;
    const __half* Am = prod ? Bdh : Bh;
    float* Out = (prod ? states : Bx) + (size_t)idx * 4096;
    wmma::fragment<wmma::accumulator, 16, 16, 16, float> acc[4];
#pragma unroll
    for (int pti = 0; pti < 4; pti++) wmma::fill_fragment(acc[pti], 0.f);
#pragma unroll
    for (int kc = 0; kc < 4; kc++) {
        wmma::fragment<wmma::matrix_a, 16, 16, 16, __half, wmma::col_major> af;
        wmma::load_matrix_sync(af, &Am[(kc * 16) * CST + ntile * 16], CST);
#pragma unroll
        for (int pti = 0; pti < 4; pti++) {
            wmma::fragment<wmma::matrix_b, 16, 16, 16, __half, wmma::row_major> bf;
            wmma::load_matrix_sync(bf, &Xh[(kc * 16) * CST + pti * 16], CST);
            wmma::mma_sync(acc[pti], af, bf, acc[pti]);
        }
    }
#pragma unroll
    for (int pti = 0; pti < 4; pti++)
        wmma::store_matrix_sync(&Out[(ntile * 16) * 64 + pti * 16], acc[pti], 64,
                                wmma::mem_row_major);
}

// ---------------- inter-chunk scan ----------------
__global__ __launch_bounds__(256) void ssd_scan_kernel(float* __restrict__ states,
                                                       const float* __restrict__ dc) {
    int bh = blockIdx.x >> 2, slice = blockIdx.x & 3;
    size_t off = (size_t)slice * 1024 + threadIdx.x * 4;
    float4 carry = make_float4(0.f, 0.f, 0.f, 0.f);
    for (int c = 0; c < NCHUNK; c++) {
        size_t base = ((size_t)bh * 64 + c) * 4096 + off;
        float dec = __ldg(&dc[bh * 64 + c]);
        float4 s = *(float4*)&states[base];
        carry.x = carry.x * dec + s.x;
        carry.y = carry.y * dec + s.y;
        carry.z = carry.z * dec + s.z;
        carry.w = carry.w * dec + s.w;
        *(float4*)&states[base] = carry;
    }
}

// ---------------- Y via wmma ----------------
__global__ __launch_bounds__(256) void ssd_y_kernel(
    const float* __restrict__ Cn, const float* __restrict__ Bx,
    const float* __restrict__ states, const float* __restrict__ rowsum,
    const float* __restrict__ expac, const float* __restrict__ skipb,
    const float* __restrict__ proj, __half* __restrict__ yg) {
    int idx = blockIdx.x;
    int c = idx & 63, h = (idx >> 6) & 31, b = idx >> 11;
    int tokbase = b * SEQLEN + c * 64;
    __shared__ __align__(16) __half Ch[64 * CST];
    __shared__ __align__(16) __half Bxh[64 * CST];
    __shared__ __align__(16) __half Sh[64 * CST];
    __shared__ float st1[64 * CST];
    __shared__ float st2[64 * CST];
    int t = threadIdx.x;
    size_t sb = (size_t)idx * 4096;
    {
        int row = t >> 2, j0 = (t & 3) * 16;
        const float* cr = Cn + (size_t)(tokbase + row) * DINNER + h * 64;
        const float* bxr = Bx + sb + row * 64;
        const float* sr = states + sb + row * 64;
#pragma unroll
        for (int j = j0; j < j0 + 16; j += 4) {
            float4 cv = *(const float4*)&cr[j];
            float4 bv = *(const float4*)&bxr[j];
            float4 sv = *(const float4*)&sr[j];
            *(__half2*)&Ch[row * CST + j] = __floats2half2_rn(cv.x, cv.y);
            *(__half2*)&Ch[row * CST + j + 2] = __floats2half2_rn(cv.z, cv.w);
            *(__half2*)&Bxh[row * CST + j] = __floats2half2_rn(bv.x, bv.y);
            *(__half2*)&Bxh[row * CST + j + 2] = __floats2half2_rn(bv.z, bv.w);
            *(__half2*)&Sh[row * CST + j] = __floats2half2_rn(sv.x, sv.y);
            *(__half2*)&Sh[row * CST + j + 2] = __floats2half2_rn(sv.z, sv.w);
        }
    }
    __syncthreads();
    int warp = t >> 5;
    int prod = warp >> 2, ltile = warp & 3;
    const __half* Bm = prod ? Sh : Bxh;
    float* St = prod ? st2 : st1;
    wmma::fragment<wmma::accumulator, 16, 16, 16, float> acc[4];
#pragma unroll
    for (int pti = 0; pti < 4; pti++) wmma::fill_fragment(acc[pti], 0.f);
#pragma unroll
    for (int kc = 0; kc < 4; kc++) {
        wmma::fragment<wmma::matrix_a, 16, 16, 16, __half, wmma::row_major> af;
        wmma::load_matrix_sync(af, &Ch[(ltile * 16) * CST + kc * 16], CST);
#pragma unroll
        for (int pti = 0; pti < 4; pti++) {
            wmma::fragment<wmma::matrix_b, 16, 16, 16, __half, wmma::row_major> bf;
            wmma::load_matrix_sync(bf, &Bm[(kc * 16) * CST + pti * 16], CST);
            wmma::mma_sync(acc[pti], af, bf, acc[pti]);
        }
    }
#pragma unroll
    for (int pti = 0; pti < 4; pti++)
        wmma::store_matrix_sync(&St[(ltile * 16) * CST + pti * 16], acc[pti], CST,
                                wmma::mem_row_major);
    __syncthreads();
    {
        int l = t >> 2, j0 = (t & 3) * 16;
        int tok = tokbase + l;
        float rs = rowsum[(size_t)idx * 64 + l];
        float ea = expac[(size_t)idx * 64 + l];
        float sk = skipb[tok * NHEADS + h];
        const float* zp = proj + (size_t)tok * PROJ + h * 64;
        __half* yo = yg + (size_t)tok * DINNER + h * 64;
#pragma unroll
        for (int j = j0; j < j0 + 16; j += 4) {
            float4 z4 = *(const float4*)&zp[j];
            float o[4];
            float zz[4] = {z4.x, z4.y, z4.z, z4.w};
#pragma unroll
            for (int q = 0; q < 4; q++) {
                float y = rs * st1[l * CST + j + q] + ea * st2[l * CST + j + q] + sk;
                o[q] = y * (zz[q] / (1.f + __expf(-zz[q]))) * YSCALE;
            }
            *(__half2*)&yo[j] = __floats2half2_rn(o[0], o[1]);
            *(__half2*)&yo[j + 2] = __floats2half2_rn(o[2], o[3]);
        }
    }
}

// ---------------- launch ----------------
extern "C" void kernel_launch(void* const* d_in, const int* in_sizes, int n_in,
                              void* d_out, int out_size) {
    (void)in_sizes; (void)n_in; (void)out_size;
    const float* x = (const float*)d_in[0];
    const float* n1w = (const float*)d_in[1];
    const float* n2w = (const float*)d_in[2];
    const float* W_in = (const float*)d_in[3];
    const float* W_out = (const float*)d_in[4];
    const float* A_log = (const float*)d_in[5];
    const float* Dp = (const float*)d_in[6];
    const float* dtbias = (const float*)d_in[7];
    const float* Bbias = (const float*)d_in[8];
    const float* Cbias = (const float*)d_in[9];
    const float* Bnw = (const float*)d_in[10];
    const float* Cnw = (const float*)d_in[11];
    const float* Wg = (const float*)d_in[12];
    const float* Wu = (const float*)d_in[13];
    const float* Wd = (const float*)d_in[14];
    float* out = (float*)d_out;

    float *proj, *xg, *Bn, *Cn, *dtb, *Ab, *skipb, *cum, *segsum, *states, *Bx;
    float *rowsum, *expac, *dc, *x2, *gb;
    __half *hh, *ygh, *gbh, *wtin, *wtout, *wtg, *wtu, *wtd;
    cudaGetSymbolAddress((void**)&proj, g_proj);
    cudaGetSymbolAddress((void**)&xg, g_xg);
    cudaGetSymbolAddress((void**)&Bn, g_Bn);
    cudaGetSymbolAddress((void**)&Cn, g_Cn);
    cudaGetSymbolAddress((void**)&dtb, g_dt);
    cudaGetSymbolAddress((void**)&Ab, g_A);
    cudaGetSymbolAddress((void**)&skipb, g_skip);
    cudaGetSymbolAddress((void**)&cum, g_cum);
    cudaGetSymbolAddress((void**)&segsum, g_segsum);
    cudaGetSymbolAddress((void**)&states, g_states);
    cudaGetSymbolAddress((void**)&Bx, g_Bx);
    cudaGetSymbolAddress((void**)&rowsum, g_rowsum);
    cudaGetSymbolAddress((void**)&expac, g_expac);
    cudaGetSymbolAddress((void**)&dc, g_dc);
    cudaGetSymbolAddress((void**)&x2, g_x2);
    cudaGetSymbolAddress((void**)&gb, g_gb);
    cudaGetSymbolAddress((void**)&hh, g_hh);
    cudaGetSymbolAddress((void**)&ygh, g_ygh);
    cudaGetSymbolAddress((void**)&gbh, g_gbh);
    cudaGetSymbolAddress((void**)&wtin, g_Wtin);
    cudaGetSymbolAddress((void**)&wtout, g_Wtout);
    cudaGetSymbolAddress((void**)&wtg, g_Wtg);
    cudaGetSymbolAddress((void**)&wtu, g_Wtu);
    cudaGetSymbolAddress((void**)&wtd, g_Wtd);
    __half* gbhalf = (__half*)gb;

    static int attr_done = 0;
    if (!attr_done) {
        cudaFuncSetAttribute(hgemm_kernel, cudaFuncAttributeMaxDynamicSharedMemorySize,
                             HG_SMEM);
        attr_done = 1;
    }

    wtransh_kernel<<<dim3(NPAD_IN / 32, DMODEL / 32), 256>>>(W_in, wtin, DMODEL, PROJ);
    wtransh_kernel<<<dim3(DMODEL / 32, DINNER / 32), 256>>>(W_out, wtout, DINNER, DMODEL);
    wtransh_kernel<<<dim3(DMLP / 32, DMODEL / 32), 256>>>(Wg, wtg, DMODEL, DMLP);
    wtransh_kernel<<<dim3(DMLP / 32, DMODEL / 32), 256>>>(Wu, wtu, DMODEL, DMLP);
    wtransh_kernel<<<dim3(DMODEL / 32, DMLP / 32), 256>>>(Wd, wtd, DMLP, DMODEL);

    // 1) hh = rmsnorm(x)
    rmsnorm_kernel<<<TOKENS, 256>>>(x, n1w, hh);
    // 2) proj = hh @ W_in
    hgemm_kernel<<<dim3(NPAD_IN / 128, TOKENS / 128), 256, HG_SMEM>>>(
        hh, wtin, nullptr, nullptr, proj, nullptr, TOKENS, PROJ, DMODEL, 0, 1.f);
    // 3) per-token preprocessing
    preproc_kernel<<<TOKENS, 256>>>(proj, A_log, Dp, dtbias, Bbias, Cbias, Bnw, Cnw, xg, Bn,
                                    Cn, dtb, Ab, skipb);
    // 4) cumtheta scan + fused RoPE
    theta_scan1<<<2 * NHEADS * 8, 1024>>>(proj, dtb, cum, segsum);
    theta_rope_kernel<<<2 * NHEADS * 8, 1024>>>(cum, segsum, Bn, Cn);
    // 5) per-chunk states/Bx (wmma) + decay scalars
    ssd_chunk_kernel<<<2 * NHEADS * NCHUNK, 256>>>(xg, Bn, Ab, states, Bx, rowsum, expac, dc);
    // 6) inter-chunk scan
    ssd_scan_kernel<<<2 * NHEADS * 4, 256>>>(states, dc);
    // 7) Y (wmma) + skip + silu(z) gate -> ygh = half(y/64)
    ssd_y_kernel<<<2 * NHEADS * NCHUNK, 256>>>(Cn, Bx, states, rowsum, expac, skipb, proj,
                                               ygh);
    // 8) x2 = x + 64*(ygh @ W_out)
    hgemm_kernel<<<dim3(DMODEL / 128, TOKENS / 128), 256, HG_SMEM>>>(
        ygh, wtout, x, nullptr, x2, nullptr, TOKENS, DMODEL, DINNER, 1, YUNSCALE);
    // 9) hh = rmsnorm(x2)
    rmsnorm_kernel<<<TOKENS, 256>>>(x2, n2w, hh);
    // 10) gbhalf = half(hh @ Wg)
    hgemm_kernel<<<dim3(DMLP / 128, TOKENS / 128), 256, HG_SMEM>>>(
        hh, wtg, nullptr, nullptr, nullptr, gbhalf, TOKENS, DMLP, DMODEL, 3, 1.f);
    // 11) gbh = half(silu(gbhalf) * (hh @ Wu))
    hgemm_kernel<<<dim3(DMLP / 128, TOKENS / 128), 256, HG_SMEM>>>(
        hh, wtu, nullptr, gbhalf, nullptr, gbh, TOKENS, DMLP, DMODEL, 2, 1.f);
    // 12) out = x2 + gbh @ Wd
    hgemm_kernel<<<dim3(DMODEL / 128, TOKENS / 128), 256, HG_SMEM>>>(
        gbh, wtd, x2, nullptr, out, nullptr, TOKENS, DMODEL, DMLP, 1, 1.f);
}

// round 17
// speedup vs baseline: 1.0984x; 1.0268x over previous
#include <cuda_runtime.h>
#include <cuda_fp16.h>
#include <mma.h>
#include <math.h>
#include <stdint.h>

using namespace nvcuda;

#define TOKENS   8192
#define SEQLEN   4096
#define DMODEL   1024
#define DINNER   2048
#define NHEADS   32
#define HEADDIM  64
#define DSTATE   64
#define CHUNKL   64
#define NCHUNK   64
#define DMLP     2560
#define PROJ     9248
#define NPAD_IN  9472
#define XS_OFF   2048
#define B_OFF    4096
#define C_OFF    6144
#define DT_OFF   8192
#define TH_OFF   8224
#define YSCALE   0.015625f
#define YUNSCALE 64.0f

// ---------------- scratch (device globals: no allocation allowed) ----------------
__device__ float g_proj[75759616];
__device__ float g_dt[TOKENS * NHEADS];
__device__ float g_A[TOKENS * NHEADS];
__device__ float g_skip[TOKENS * NHEADS];
__device__ float g_cum[TOKENS * NHEADS * (DSTATE / 2)];
__device__ float g_segsum[2 * NHEADS * 8 * 32];
__device__ float g_states[2 * NHEADS * NCHUNK * HEADDIM * DSTATE];
__device__ float g_Bx[2 * NHEADS * NCHUNK * HEADDIM * DSTATE];
__device__ float g_rowsum[2 * NHEADS * NCHUNK * CHUNKL];
__device__ float g_expac[2 * NHEADS * NCHUNK * CHUNKL];
__device__ float g_dc[2 * NHEADS * NCHUNK];
__device__ float g_x2[TOKENS * DMODEL];
__device__ __align__(16) float g_gb[TOKENS * DMLP];  // hosts half gb (cast)
__device__ __align__(16) __half g_xgh[TOKENS * DINNER];
__device__ __align__(16) __half g_Bnh[TOKENS * DINNER];
__device__ __align__(16) __half g_Cnh[TOKENS * DINNER];
__device__ __align__(16) __half g_hh[TOKENS * DMODEL];
__device__ __align__(16) __half g_ygh[TOKENS * DINNER];
__device__ __align__(16) __half g_gbh[TOKENS * DMLP];
__device__ __align__(16) __half g_Wtin[NPAD_IN * DMODEL];
__device__ __align__(16) __half g_Wtout[DMODEL * DINNER];
__device__ __align__(16) __half g_Wtg[DMLP * DMODEL];
__device__ __align__(16) __half g_Wtu[DMLP * DMODEL];
__device__ __align__(16) __half g_Wtd[DMODEL * DMLP];

// ---------------- helpers ----------------
__device__ __forceinline__ void cp16(void* smem, const void* g) {
    uint32_t s = (uint32_t)__cvta_generic_to_shared(smem);
    asm volatile("cp.async.cg.shared.global [%0], [%1], 16;" ::"r"(s), "l"(g));
}

// ---------------- weight transpose + fp16 convert: in[K][N] -> out[Npad][K] ----------------
__global__ __launch_bounds__(256) void wtransh_kernel(const float* __restrict__ in,
                                                      __half* __restrict__ out, int K, int N) {
    __shared__ float tile[32][33];
    int n0 = blockIdx.x * 32, k0 = blockIdx.y * 32;
    int tx = threadIdx.x & 31, ty = threadIdx.x >> 5;
#pragma unroll
    for (int i = ty; i < 32; i += 8) {
        int n = n0 + tx;
        tile[i][tx] = (n < N) ? in[(size_t)(k0 + i) * N + n] : 0.f;
    }
    __syncthreads();
#pragma unroll
    for (int i = ty; i < 32; i += 8)
        out[(size_t)(n0 + i) * K + k0 + tx] = __float2half_rn(tile[tx][i]);
}

// ---------------- FP16 wmma GEMM (256 thr, 2x4 warps, 64x32 tile, BK=64) --------------
// mode 0: C=v; 1: C=v+Res; 2: Ch=half(silu(ResH)*v); 3: Ch=half(v)   (v = ascale*acc)
#define AST 72
#define HBUF (128 * AST)
#define HG_SMEM (4 * HBUF * 2)
__global__ __launch_bounds__(256, 2) void hgemm_kernel(const __half* __restrict__ A,
                                                       const __half* __restrict__ Bt,
                                                       const float* __restrict__ Res,
                                                       const __half* __restrict__ ResH,
                                                       float* __restrict__ C,
                                                       __half* __restrict__ Ch,
                                                       int M, int N, int K, int mode,
                                                       float ascale) {
    extern __shared__ __align__(16) __half smem_h[];
    __half* As0 = smem_h;
    __half* Bs0 = smem_h + 2 * HBUF;
    float* stage = (float*)smem_h;

    int bm = blockIdx.y * 128, bn = blockIdx.x * 128;
    int t = threadIdx.x;
    int warp = t >> 5;
    int wm = warp & 1, wn = warp >> 1;
    int lrow = t >> 3, lcol = (t & 7) * 8;

    wmma::fragment<wmma::accumulator, 16, 16, 16, float> acc[4][2];
#pragma unroll
    for (int mi = 0; mi < 4; mi++)
#pragma unroll
        for (int nn = 0; nn < 2; nn++) wmma::fill_fragment(acc[mi][nn], 0.f);

    auto issue = [&](int buf, int k0) {
        __half* as = As0 + buf * HBUF;
        __half* bs = Bs0 + buf * HBUF;
#pragma unroll
        for (int r = 0; r < 4; r++) {
            int row = lrow + r * 32;
            cp16(&as[row * AST + lcol], A + (size_t)(bm + row) * K + k0 + lcol);
            cp16(&bs[row * AST + lcol], Bt + (size_t)(bn + row) * K + k0 + lcol);
        }
        asm volatile("cp.async.commit_group;");
    };

    int nk = K / 64;
    issue(0, 0);
    for (int it = 0; it < nk; it++) {
        int buf = it & 1;
        if (it + 1 < nk) {
            issue(buf ^ 1, (it + 1) * 64);
            asm volatile("cp.async.wait_group 1;");
        } else {
            asm volatile("cp.async.wait_group 0;");
        }
        __syncthreads();
        const __half* as = As0 + buf * HBUF;
        const __half* bs = Bs0 + buf * HBUF;
#pragma unroll
        for (int kk = 0; kk < 64; kk += 16) {
            wmma::fragment<wmma::matrix_a, 16, 16, 16, __half, wmma::row_major> af[4];
            wmma::fragment<wmma::matrix_b, 16, 16, 16, __half, wmma::col_major> bf[2];
#pragma unroll
            for (int mi = 0; mi < 4; mi++)
                wmma::load_matrix_sync(af[mi], &as[(wm * 64 + mi * 16) * AST + kk], AST);
#pragma unroll
            for (int nn = 0; nn < 2; nn++)
                wmma::load_matrix_sync(bf[nn], &bs[(wn * 32 + nn * 16) * AST + kk], AST);
#pragma unroll
            for (int mi = 0; mi < 4; mi++)
#pragma unroll
                for (int nn = 0; nn < 2; nn++)
                    wmma::mma_sync(acc[mi][nn], af[mi], bf[nn], acc[mi][nn]);
        }
        __syncthreads();
    }

    if (mode <= 1 && bn + 128 <= N) {
#pragma unroll
        for (int mi = 0; mi < 4; mi++) {
#pragma unroll
            for (int nn = 0; nn < 2; nn++) {
                size_t off = (size_t)(bm + wm * 64 + mi * 16) * N + bn + wn * 32 + nn * 16;
                if (mode == 1) {
                    wmma::fragment<wmma::accumulator, 16, 16, 16, float> rf;
                    wmma::load_matrix_sync(rf, Res + off, N, wmma::mem_row_major);
#pragma unroll
                    for (int e = 0; e < rf.num_elements; e++)
                        acc[mi][nn].x[e] = acc[mi][nn].x[e] * ascale + rf.x[e];
                } else if (ascale != 1.f) {
#pragma unroll
                    for (int e = 0; e < acc[mi][nn].num_elements; e++)
                        acc[mi][nn].x[e] *= ascale;
                }
                wmma::store_matrix_sync(C + off, acc[mi][nn], N, wmma::mem_row_major);
            }
        }
        return;
    }

    for (int p = 0; p < 2; p++) {
        __syncthreads();
        if (wm == p) {
#pragma unroll
            for (int mi = 0; mi < 4; mi++)
#pragma unroll
                for (int nn = 0; nn < 2; nn++)
                    wmma::store_matrix_sync(&stage[(mi * 16) * 136 + wn * 32 + nn * 16],
                                            acc[mi][nn], 136, wmma::mem_row_major);
        }
        __syncthreads();
#pragma unroll 4
        for (int u = t; u < 64 * 64; u += 256) {
            int row = u >> 6, c2 = (u & 63) * 2;
            int gc = bn + c2;
            if (gc < N) {
                int gr = bm + p * 64 + row;
                float v0 = stage[row * 136 + c2] * ascale;
                float v1 = stage[row * 136 + c2 + 1] * ascale;
                size_t go = (size_t)gr * N + gc;
                if (mode == 2) {
                    float2 rr = __half22float2(*(const __half2*)&ResH[go]);
                    v0 = rr.x / (1.f + __expf(-rr.x)) * v0;
                    v1 = rr.y / (1.f + __expf(-rr.y)) * v1;
                    *(__half2*)&Ch[go] = __floats2half2_rn(v0, v1);
                } else if (mode == 3) {
                    *(__half2*)&Ch[go] = __floats2half2_rn(v0, v1);
                } else {
                    if (mode == 1) {
                        v0 += Res[go];
                        v1 += Res[go + 1];
                    }
                    *(float2*)&C[go] = make_float2(v0, v1);
                }
            }
        }
    }
}

// ---------------- rmsnorm over D=1024 (half output) ----------------
__global__ __launch_bounds__(256) void rmsnorm_kernel(const float* __restrict__ x,
                                                      const float* __restrict__ w,
                                                      __half* __restrict__ out) {
    int row = blockIdx.x;
    const float* xr = x + (size_t)row * DMODEL;
    float v[4];
    float s = 0.f;
#pragma unroll
    for (int i = 0; i < 4; i++) {
        v[i] = xr[threadIdx.x + i * 256];
        s += v[i] * v[i];
    }
    __shared__ float red[8];
#pragma unroll
    for (int o = 16; o; o >>= 1) s += __shfl_xor_sync(0xffffffffu, s, o);
    if ((threadIdx.x & 31) == 0) red[threadIdx.x >> 5] = s;
    __syncthreads();
    if (threadIdx.x == 0) {
        float tt = 0.f;
#pragma unroll
        for (int i = 0; i < 8; i++) tt += red[i];
        red[0] = rsqrtf(tt / (float)DMODEL + 1e-5f);
    }
    __syncthreads();
    float r = red[0];
#pragma unroll
    for (int i = 0; i < 4; i++) {
        int c = threadIdx.x + i * 256;
        out[(size_t)row * DMODEL + c] = __float2half_rn(v[i] * r * w[c]);
    }
}

// ---------------- per-token preprocessing (half xg/Bn/Cn outputs) ----------------
__global__ __launch_bounds__(256) void preproc_kernel(
    const float* __restrict__ proj, const float* __restrict__ A_log,
    const float* __restrict__ D_param, const float* __restrict__ dt_bias,
    const float* __restrict__ B_bias, const float* __restrict__ C_bias,
    const float* __restrict__ Bn_w, const float* __restrict__ Cn_w,
    __half* __restrict__ xgh, __half* __restrict__ Bnh, __half* __restrict__ Cnh,
    float* __restrict__ dtb, float* __restrict__ Ab, float* __restrict__ skipb) {
    int tok = blockIdx.x;
    const float* p = proj + (size_t)tok * PROJ;
    int warp = threadIdx.x >> 5, lane = threadIdx.x & 31;
    for (int h = warp; h < NHEADS; h += 8) {
        float xb = p[DT_OFF + h] + dt_bias[h];
        float dt = xb > 20.f ? xb : log1pf(expf(xb));
        float Av = -expf(A_log[h]) * dt;
        float alpha = expf(Av);
        float gamma = (alpha - 1.f) / (Av + 1e-6f) * 0.5f + 1.f;
        if (lane == 0) {
            dtb[tok * NHEADS + h] = dt;
            Ab[tok * NHEADS + h] = Av;
        }
        float xs0 = p[XS_OFF + h * 64 + lane];
        float xs1 = p[XS_OFF + h * 64 + 32 + lane];
        float ssum = xs0 + xs1;
#pragma unroll
        for (int o = 16; o; o >>= 1) ssum += __shfl_xor_sync(0xffffffffu, ssum, o);
        if (lane == 0) skipb[tok * NHEADS + h] = D_param[h] * ssum;
        size_t ob = (size_t)tok * DINNER + h * 64;
        xgh[ob + lane] = __float2half_rn(xs0 * gamma);
        xgh[ob + 32 + lane] = __float2half_rn(xs1 * gamma);
        float b0 = p[B_OFF + h * 64 + lane], b1 = p[B_OFF + h * 64 + 32 + lane];
        float bs = b0 * b0 + b1 * b1;
#pragma unroll
        for (int o = 16; o; o >>= 1) bs += __shfl_xor_sync(0xffffffffu, bs, o);
        float br = rsqrtf(bs / 64.f + 1e-5f);
        Bnh[ob + lane] = __float2half_rn(b0 * br * Bn_w[lane] + B_bias[h * 64 + lane]);
        Bnh[ob + 32 + lane] =
            __float2half_rn(b1 * br * Bn_w[32 + lane] + B_bias[h * 64 + 32 + lane]);
        float c0 = p[C_OFF + h * 64 + lane], c1 = p[C_OFF + h * 64 + 32 + lane];
        float cs = c0 * c0 + c1 * c1;
#pragma unroll
        for (int o = 16; o; o >>= 1) cs += __shfl_xor_sync(0xffffffffu, cs, o);
        float cr = rsqrtf(cs / 64.f + 1e-5f);
        Cnh[ob + lane] = __float2half_rn(c0 * cr * Cn_w[lane] + C_bias[h * 64 + lane]);
        Cnh[ob + 32 + lane] =
            __float2half_rn(c1 * cr * Cn_w[32 + lane] + C_bias[h * 64 + 32 + lane]);
    }
}

// ---------------- theta cumsum pass 1 ----------------
__global__ __launch_bounds__(1024) void theta_scan1(const float* __restrict__ proj,
                                                    const float* __restrict__ dtb,
                                                    float* __restrict__ cum,
                                                    float* __restrict__ segsum) {
    int blk = blockIdx.x;
    int seg = blk & 7, h = (blk >> 3) & 31, b = blk >> 8;
    int w = threadIdx.x >> 5, lane = threadIdx.x & 31;
    __shared__ float T[32][33];
    __shared__ float O[32][33];
    __shared__ float Dt[32];
    int s0 = b * SEQLEN + seg * 512;
    float carry = 0.f;
    for (int it = 0; it < 16; it++) {
        int tk = s0 + it * 32;
        T[w][lane] = proj[(size_t)(tk + w) * PROJ + TH_OFF + h * 32 + lane];
        if (w == 0) Dt[lane] = dtb[(tk + lane) * NHEADS + h];
        __syncthreads();
        float v = Dt[lane] * T[lane][w];
#pragma unroll
        for (int o = 1; o < 32; o <<= 1) {
            float tv = __shfl_up_sync(0xffffffffu, v, o);
            if (lane >= o) v += tv;
        }
        v += carry;
        float cnew = __shfl_sync(0xffffffffu, v, 31);
        O[lane][w] = v;
        __syncthreads();
        cum[(size_t)(tk + w) * 1024 + h * 32 + lane] = O[w][lane];
        carry = cnew;
    }
    if (lane == 0) segsum[blk * 32 + w] = carry;
}

// ---------------- pass 2 fused with RoPE (half in/out) ----------------
__global__ __launch_bounds__(1024) void theta_rope_kernel(const float* __restrict__ cum,
                                                          const float* __restrict__ segsum,
                                                          __half* __restrict__ Bnh,
                                                          __half* __restrict__ Cnh) {
    int blk = blockIdx.x;
    int seg = blk & 7, h = (blk >> 3) & 31, b = blk >> 8;
    int w = threadIdx.x >> 5, lane = threadIdx.x & 31;
    int bh8 = (b * 32 + h) * 8;
    float off = 0.f;
    for (int s = 0; s < seg; s++) off += segsum[(bh8 + s) * 32 + lane];
    int s0 = b * SEQLEN + seg * 512;
    for (int it = 0; it < 16; it++) {
        int tok = s0 + it * 32 + w;
        float ang = cum[(size_t)tok * 1024 + h * 32 + lane] + off;
        float sn, cs;
        __sincosf(ang, &sn, &cs);
        size_t base = (size_t)tok * DINNER + h * 64 + 2 * lane;
        float2 bv = __half22float2(*(__half2*)&Bnh[base]);
        *(__half2*)&Bnh[base] =
            __floats2half2_rn(cs * bv.x - sn * bv.y, sn * bv.x + cs * bv.y);
        float2 cv = __half22float2(*(__half2*)&Cnh[base]);
        *(__half2*)&Cnh[base] =
            __floats2half2_rn(cs * cv.x - sn * cv.y, sn * cv.x + cs * cv.y);
    }
}

// ---------------- per-chunk via wmma (half inputs) ----------------
#define CST 72
__global__ __launch_bounds__(256) void ssd_chunk_kernel(
    const __half* __restrict__ xgh, const __half* __restrict__ Bnh,
    const float* __restrict__ Ab, float* __restrict__ states, float* __restrict__ Bx,
    float* __restrict__ rowsum, float* __restrict__ expac, float* __restrict__ dc) {
    int idx = blockIdx.x;
    int c = idx & 63, h = (idx >> 6) & 31, b = idx >> 11;
    int tokbase = b * SEQLEN + c * 64;
    __shared__ __align__(16) __half Bh[64 * CST];
    __shared__ __align__(16) __half Bdh[64 * CST];
    __shared__ __align__(16) __half Xh[64 * CST];
    __shared__ float Ac[64];
    __shared__ float decs[64];
    int t = threadIdx.x;
    int lane = t & 31;
    if (t < 64) {
        float v = Ab[(tokbase + t) * NHEADS + h];
#pragma unroll
        for (int o = 1; o < 32; o <<= 1) {
            float tv = __shfl_up_sync(0xffffffffu, v, o);
            if (lane >= o) v += tv;
        }
        Ac[t] = v;
    }
    __syncthreads();
    if (t >= 32 && t < 64) Ac[t] += Ac[31];
    __syncthreads();
    float alast = Ac[63];
    if (t < 64) {
        decs[t] = __expf(alast - Ac[t]);
        expac[(size_t)idx * 64 + t] = __expf(Ac[t]);
        float rs = 64.f - (float)t;
        float act = Ac[t];
        for (int s2 = 0; s2 < t; s2++) rs += __expf(act - Ac[s2]);
        rowsum[(size_t)idx * 64 + t] = rs;
    }
    if (t == 0) dc[idx] = __expf(alast);
    __syncthreads();
    {
        int row = t >> 2, j0 = (t & 3) * 16;
        float dv = decs[row];
        const __half* br = Bnh + (size_t)(tokbase + row) * DINNER + h * 64;
        const __half* xr = xgh + (size_t)(tokbase + row) * DINNER + h * 64;
        *(uint4*)&Bh[row * CST + j0] = *(const uint4*)&br[j0];
        *(uint4*)&Bh[row * CST + j0 + 8] = *(const uint4*)&br[j0 + 8];
        *(uint4*)&Xh[row * CST + j0] = *(const uint4*)&xr[j0];
        *(uint4*)&Xh[row * CST + j0 + 8] = *(const uint4*)&xr[j0 + 8];
#pragma unroll
        for (int j = j0; j < j0 + 16; j += 2) {
            float2 bf = __half22float2(*(const __half2*)&br[j]);
            *(__half2*)&Bdh[row * CST + j] = __floats2half2_rn(bf.x * dv, bf.y * dv);
        }
    }
    __syncthreads();
    int warp = t >> 5;
    int prod = warp >> 2, ntile = warp & 3;
    const __half* Am = prod ? Bdh : Bh;
    float* Out = (prod ? states : Bx) + (size_t)idx * 4096;
    wmma::fragment<wmma::accumulator, 16, 16, 16, float> acc[4];
#pragma unroll
    for (int pti = 0; pti < 4; pti++) wmma::fill_fragment(acc[pti], 0.f);
#pragma unroll
    for (int kc = 0; kc < 4; kc++) {
        wmma::fragment<wmma::matrix_a, 16, 16, 16, __half, wmma::col_major> af;
        wmma::load_matrix_sync(af, &Am[(kc * 16) * CST + ntile * 16], CST);
#pragma unroll
        for (int pti = 0; pti < 4; pti++) {
            wmma::fragment<wmma::matrix_b, 16, 16, 16, __half, wmma::row_major> bf;
            wmma::load_matrix_sync(bf, &Xh[(kc * 16) * CST + pti * 16], CST);
            wmma::mma_sync(acc[pti], af, bf, acc[pti]);
        }
    }
#pragma unroll
    for (int pti = 0; pti < 4; pti++)
        wmma::store_matrix_sync(&Out[(ntile * 16) * 64 + pti * 16], acc[pti], 64,
                                wmma::mem_row_major);
}

// ---------------- inter-chunk scan ----------------
__global__ __launch_bounds__(256) void ssd_scan_kernel(float* __restrict__ states,
                                                       const float* __restrict__ dc) {
    int bh = blockIdx.x >> 2, slice = blockIdx.x & 3;
    size_t off = (size_t)slice * 1024 + threadIdx.x * 4;
    float4 carry = make_float4(0.f, 0.f, 0.f, 0.f);
    for (int c = 0; c < NCHUNK; c++) {
        size_t base = ((size_t)bh * 64 + c) * 4096 + off;
        float dec = __ldg(&dc[bh * 64 + c]);
        float4 s = *(float4*)&states[base];
        carry.x = carry.x * dec + s.x;
        carry.y = carry.y * dec + s.y;
        carry.z = carry.z * dec + s.z;
        carry.w = carry.w * dec + s.w;
        *(float4*)&states[base] = carry;
    }
}

// ---------------- Y via wmma (half C input) ----------------
__global__ __launch_bounds__(256) void ssd_y_kernel(
    const __half* __restrict__ Cnh, const float* __restrict__ Bx,
    const float* __restrict__ states, const float* __restrict__ rowsum,
    const float* __restrict__ expac, const float* __restrict__ skipb,
    const float* __restrict__ proj, __half* __restrict__ yg) {
    int idx = blockIdx.x;
    int c = idx & 63, h = (idx >> 6) & 31, b = idx >> 11;
    int tokbase = b * SEQLEN + c * 64;
    __shared__ __align__(16) __half Ch[64 * CST];
    __shared__ __align__(16) __half Bxh[64 * CST];
    __shared__ __align__(16) __half Sh[64 * CST];
    __shared__ float st1[64 * CST];
    __shared__ float st2[64 * CST];
    int t = threadIdx.x;
    size_t sb = (size_t)idx * 4096;
    {
        int row = t >> 2, j0 = (t & 3) * 16;
        const __half* cr = Cnh + (size_t)(tokbase + row) * DINNER + h * 64;
        const float* bxr = Bx + sb + row * 64;
        const float* sr = states + sb + row * 64;
        *(uint4*)&Ch[row * CST + j0] = *(const uint4*)&cr[j0];
        *(uint4*)&Ch[row * CST + j0 + 8] = *(const uint4*)&cr[j0 + 8];
#pragma unroll
        for (int j = j0; j < j0 + 16; j += 4) {
            float4 bv = *(const float4*)&bxr[j];
            float4 sv = *(const float4*)&sr[j];
            *(__half2*)&Bxh[row * CST + j] = __floats2half2_rn(bv.x, bv.y);
            *(__half2*)&Bxh[row * CST + j + 2] = __floats2half2_rn(bv.z, bv.w);
            *(__half2*)&Sh[row * CST + j] = __floats2half2_rn(sv.x, sv.y);
            *(__half2*)&Sh[row * CST + j + 2] = __floats2half2_rn(sv.z, sv.w);
        }
    }
    __syncthreads();
    int warp = t >> 5;
    int prod = warp >> 2, ltile = warp & 3;
    const __half* Bm = prod ? Sh : Bxh;
    float* St = prod ? st2 : st1;
    wmma::fragment<wmma::accumulator, 16, 16, 16, float> acc[4];
#pragma unroll
    for (int pti = 0; pti < 4; pti++) wmma::fill_fragment(acc[pti], 0.f);
#pragma unroll
    for (int kc = 0; kc < 4; kc++) {
        wmma::fragment<wmma::matrix_a, 16, 16, 16, __half, wmma::row_major> af;
        wmma::load_matrix_sync(af, &Ch[(ltile * 16) * CST + kc * 16], CST);
#pragma unroll
        for (int pti = 0; pti < 4; pti++) {
            wmma::fragment<wmma::matrix_b, 16, 16, 16, __half, wmma::row_major> bf;
            wmma::load_matrix_sync(bf, &Bm[(kc * 16) * CST + pti * 16], CST);
            wmma::mma_sync(acc[pti], af, bf, acc[pti]);
        }
    }
#pragma unroll
    for (int pti = 0; pti < 4; pti++)
        wmma::store_matrix_sync(&St[(ltile * 16) * CST + pti * 16], acc[pti], CST,
                                wmma::mem_row_major);
    __syncthreads();
    {
        int l = t >> 2, j0 = (t & 3) * 16;
        int tok = tokbase + l;
        float rs = rowsum[(size_t)idx * 64 + l];
        float ea = expac[(size_t)idx * 64 + l];
        float sk = skipb[tok * NHEADS + h];
        const float* zp = proj + (size_t)tok * PROJ + h * 64;
        __half* yo = yg + (size_t)tok * DINNER + h * 64;
#pragma unroll
        for (int j = j0; j < j0 + 16; j += 4) {
            float4 z4 = *(const float4*)&zp[j];
            float o[4];
            float zz[4] = {z4.x, z4.y, z4.z, z4.w};
#pragma unroll
            for (int q = 0; q < 4; q++) {
                float y = rs * st1[l * CST + j + q] + ea * st2[l * CST + j + q] + sk;
                o[q] = y * (zz[q] / (1.f + __expf(-zz[q]))) * YSCALE;
            }
            *(__half2*)&yo[j] = __floats2half2_rn(o[0], o[1]);
            *(__half2*)&yo[j + 2] = __floats2half2_rn(o[2], o[3]);
        }
    }
}

// ---------------- launch ----------------
extern "C" void kernel_launch(void* const* d_in, const int* in_sizes, int n_in,
                              void* d_out, int out_size) {
    (void)in_sizes; (void)n_in; (void)out_size;
    const float* x = (const float*)d_in[0];
    const float* n1w = (const float*)d_in[1];
    const float* n2w = (const float*)d_in[2];
    const float* W_in = (const float*)d_in[3];
    const float* W_out = (const float*)d_in[4];
    const float* A_log = (const float*)d_in[5];
    const float* Dp = (const float*)d_in[6];
    const float* dtbias = (const float*)d_in[7];
    const float* Bbias = (const float*)d_in[8];
    const float* Cbias = (const float*)d_in[9];
    const float* Bnw = (const float*)d_in[10];
    const float* Cnw = (const float*)d_in[11];
    const float* Wg = (const float*)d_in[12];
    const float* Wu = (const float*)d_in[13];
    const float* Wd = (const float*)d_in[14];
    float* out = (float*)d_out;

    float *proj, *dtb, *Ab, *skipb, *cum, *segsum, *states, *Bx;
    float *rowsum, *expac, *dc, *x2, *gb;
    __half *xgh, *Bnh, *Cnh, *hh, *ygh, *gbh, *wtin, *wtout, *wtg, *wtu, *wtd;
    cudaGetSymbolAddress((void**)&proj, g_proj);
    cudaGetSymbolAddress((void**)&dtb, g_dt);
    cudaGetSymbolAddress((void**)&Ab, g_A);
    cudaGetSymbolAddress((void**)&skipb, g_skip);
    cudaGetSymbolAddress((void**)&cum, g_cum);
    cudaGetSymbolAddress((void**)&segsum, g_segsum);
    cudaGetSymbolAddress((void**)&states, g_states);
    cudaGetSymbolAddress((void**)&Bx, g_Bx);
    cudaGetSymbolAddress((void**)&rowsum, g_rowsum);
    cudaGetSymbolAddress((void**)&expac, g_expac);
    cudaGetSymbolAddress((void**)&dc, g_dc);
    cudaGetSymbolAddress((void**)&x2, g_x2);
    cudaGetSymbolAddress((void**)&gb, g_gb);
    cudaGetSymbolAddress((void**)&xgh, g_xgh);
    cudaGetSymbolAddress((void**)&Bnh, g_Bnh);
    cudaGetSymbolAddress((void**)&Cnh, g_Cnh);
    cudaGetSymbolAddress((void**)&hh, g_hh);
    cudaGetSymbolAddress((void**)&ygh, g_ygh);
    cudaGetSymbolAddress((void**)&gbh, g_gbh);
    cudaGetSymbolAddress((void**)&wtin, g_Wtin);
    cudaGetSymbolAddress((void**)&wtout, g_Wtout);
    cudaGetSymbolAddress((void**)&wtg, g_Wtg);
    cudaGetSymbolAddress((void**)&wtu, g_Wtu);
    cudaGetSymbolAddress((void**)&wtd, g_Wtd);
    __half* gbhalf = (__half*)gb;

    static int attr_done = 0;
    if (!attr_done) {
        cudaFuncSetAttribute(hgemm_kernel, cudaFuncAttributeMaxDynamicSharedMemorySize,
                             HG_SMEM);
        attr_done = 1;
    }

    wtransh_kernel<<<dim3(NPAD_IN / 32, DMODEL / 32), 256>>>(W_in, wtin, DMODEL, PROJ);
    wtransh_kernel<<<dim3(DMODEL / 32, DINNER / 32), 256>>>(W_out, wtout, DINNER, DMODEL);
    wtransh_kernel<<<dim3(DMLP / 32, DMODEL / 32), 256>>>(Wg, wtg, DMODEL, DMLP);
    wtransh_kernel<<<dim3(DMLP / 32, DMODEL / 32), 256>>>(Wu, wtu, DMODEL, DMLP);
    wtransh_kernel<<<dim3(DMODEL / 32, DMLP / 32), 256>>>(Wd, wtd, DMLP, DMODEL);

    // 1) hh = rmsnorm(x)
    rmsnorm_kernel<<<TOKENS, 256>>>(x, n1w, hh);
    // 2) proj = hh @ W_in
    hgemm_kernel<<<dim3(NPAD_IN / 128, TOKENS / 128), 256, HG_SMEM>>>(
        hh, wtin, nullptr, nullptr, proj, nullptr, TOKENS, PROJ, DMODEL, 0, 1.f);
    // 3) per-token preprocessing (half outputs)
    preproc_kernel<<<TOKENS, 256>>>(proj, A_log, Dp, dtbias, Bbias, Cbias, Bnw, Cnw, xgh,
                                    Bnh, Cnh, dtb, Ab, skipb);
    // 4) cumtheta scan + fused RoPE (half B/C in place)
    theta_scan1<<<2 * NHEADS * 8, 1024>>>(proj, dtb, cum, segsum);
    theta_rope_kernel<<<2 * NHEADS * 8, 1024>>>(cum, segsum, Bnh, Cnh);
    // 5) per-chunk states/Bx (wmma, half inputs) + decay scalars
    ssd_chunk_kernel<<<2 * NHEADS * NCHUNK, 256>>>(xgh, Bnh, Ab, states, Bx, rowsum, expac,
                                                   dc);
    // 6) inter-chunk scan
    ssd_scan_kernel<<<2 * NHEADS * 4, 256>>>(states, dc);
    // 7) Y (wmma) + skip + silu(z) gate -> ygh = half(y/64)
    ssd_y_kernel<<<2 * NHEADS * NCHUNK, 256>>>(Cnh, Bx, states, rowsum, expac, skipb, proj,
                                               ygh);
    // 8) x2 = x + 64*(ygh @ W_out)
    hgemm_kernel<<<dim3(DMODEL / 128, TOKENS / 128), 256, HG_SMEM>>>(
        ygh, wtout, x, nullptr, x2, nullptr, TOKENS, DMODEL, DINNER, 1, YUNSCALE);
    // 9) hh = rmsnorm(x2)
    rmsnorm_kernel<<<TOKENS, 256>>>(x2, n2w, hh);
    // 10) gbhalf = half(hh @ Wg)
    hgemm_kernel<<<dim3(DMLP / 128, TOKENS / 128), 256, HG_SMEM>>>(
        hh, wtg, nullptr, nullptr, nullptr, gbhalf, TOKENS, DMLP, DMODEL, 3, 1.f);
    // 11) gbh = half(silu(gbhalf) * (hh @ Wu))
    hgemm_kernel<<<dim3(DMLP / 128, TOKENS / 128), 256, HG_SMEM>>>(
        hh, wtu, nullptr, gbhalf, nullptr, gbh, TOKENS, DMLP, DMODEL, 2, 1.f);
    // 12) out = x2 + gbh @ Wd
    hgemm_kernel<<<dim3(DMODEL / 128, TOKENS / 128), 256, HG_SMEM>>>(
        gbh, wtd, x2, nullptr, out, nullptr, TOKENS, DMODEL, DMLP, 1, 1.f);
}